// round 3
// baseline (speedup 1.0000x reference)
#include <cuda_runtime.h>
#include <cstdint>
#include <cstdio>

// Problem constants
#define NL   6
#define NH   8
#define DMOD 512
#define DKV  64
#define DFF  2048
#define NB   8
#define SEQ  512
#define NTOK 4096          // NB*SEQ
#define NHB  64            // NH*NB

#define X_ELEMS   (NTOK*DMOD)                 // 2,097,152
#define ATT_PER_L ((size_t)NHB*SEQ*SEQ)       // 16,777,216
#define SLF_OFF   ((size_t)X_ELEMS)
#define ENC_OFF   (SLF_OFF + (size_t)NL*ATT_PER_L)
#define FULL_OUT  (ENC_OFF + (size_t)NL*ATT_PER_L)   // 203,423,744

// ---------------- scratch (no allocations allowed) ----------------
__device__ float g_x [NTOK*DMOD];
__device__ float g_q [NHB*SEQ*DKV];
__device__ float g_k [NHB*SEQ*DKV];
__device__ float g_v [NHB*SEQ*DKV];
__device__ float g_ao[NTOK*DMOD];
__device__ float g_y [NTOK*DMOD];
__device__ float g_h [NTOK*DFF];
__device__ float g_wrep[NL*6*DMOD*DMOD];     // repacked per-head weights [D, H*DK]

// ---------------- embedding ----------------
__global__ void embed_k(const int* __restrict__ seq, const int* __restrict__ pos,
                        const float* __restrict__ wemb, const float* __restrict__ pemb,
                        float* __restrict__ x) {
    int n = blockIdx.x;
    int s = seq[n], p = pos[n];
    const float* we = wemb + (size_t)s * DMOD;
    const float* pe = pemb + (size_t)p * DMOD;
    for (int c = threadIdx.x; c < DMOD; c += blockDim.x)
        x[(size_t)n * DMOD + c] = we[c] + pe[c];
}

// ---------------- weight repack: [H,D,DK] -> [D, H*DK] ----------------
__global__ void repack_k(const float* __restrict__ src, float* __restrict__ dst) {
    int o = blockIdx.x * 256 + threadIdx.x;   // 262144 total
    int d = o >> 9, h = (o >> 6) & 7, e = o & 63;
    dst[o] = src[h * (DMOD * DKV) + d * DKV + e];
}

// ---------------- SGEMM 128x128x16, 256 threads, 8x8 per thread ----------------
// mode: 0 plain, 1 +bias, 2 relu(+bias), 3 qkv-scatter (C laid out [h*NB+b][t][e])
__global__ __launch_bounds__(256) void sgemm_k(
    const float* __restrict__ A, const float* __restrict__ B,
    const float* __restrict__ bias, float* __restrict__ C,
    int M, int N, int K, int mode)
{
    __shared__ float As[16][132];
    __shared__ float Bs[16][132];
    const int tid = threadIdx.x;
    const int bm = blockIdx.y, bn = blockIdx.x;
    const float* Ab = A + (size_t)bm * 128 * K;
    const float* Bb = B + bn * 128;

    float acc[8][8];
#pragma unroll
    for (int i = 0; i < 8; i++)
#pragma unroll
        for (int j = 0; j < 8; j++) acc[i][j] = 0.f;

    const int tr = tid >> 4, tc = tid & 15;
    const int m0 = tr * 8, n0 = tc * 8;
    const int ar = tid >> 2, ac4 = tid & 3;
    const int br = tid >> 5, bc4 = tid & 31;

    for (int k0 = 0; k0 < K; k0 += 16) {
        float4 a0 = *(const float4*)(Ab + (size_t)ar * K + k0 + ac4 * 4);
        float4 a1 = *(const float4*)(Ab + (size_t)(ar + 64) * K + k0 + ac4 * 4);
        float4 b0 = *(const float4*)(Bb + (size_t)(k0 + br) * N + bc4 * 4);
        float4 b1 = *(const float4*)(Bb + (size_t)(k0 + br + 8) * N + bc4 * 4);
        __syncthreads();
        As[ac4 * 4 + 0][ar] = a0.x; As[ac4 * 4 + 1][ar] = a0.y;
        As[ac4 * 4 + 2][ar] = a0.z; As[ac4 * 4 + 3][ar] = a0.w;
        As[ac4 * 4 + 0][ar + 64] = a1.x; As[ac4 * 4 + 1][ar + 64] = a1.y;
        As[ac4 * 4 + 2][ar + 64] = a1.z; As[ac4 * 4 + 3][ar + 64] = a1.w;
        *(float4*)&Bs[br][bc4 * 4]     = b0;
        *(float4*)&Bs[br + 8][bc4 * 4] = b1;
        __syncthreads();
#pragma unroll
        for (int kk = 0; kk < 16; kk++) {
            float a[8], b[8];
            *(float4*)(a)     = *(const float4*)&As[kk][m0];
            *(float4*)(a + 4) = *(const float4*)&As[kk][m0 + 4];
            *(float4*)(b)     = *(const float4*)&Bs[kk][n0];
            *(float4*)(b + 4) = *(const float4*)&Bs[kk][n0 + 4];
#pragma unroll
            for (int i = 0; i < 8; i++)
#pragma unroll
                for (int j = 0; j < 8; j++) acc[i][j] = fmaf(a[i], b[j], acc[i][j]);
        }
    }

    if (mode == 3) {
#pragma unroll
        for (int i = 0; i < 8; i++) {
            int row = bm * 128 + m0 + i;
            int b_ = row >> 9, t = row & 511;
#pragma unroll
            for (int j = 0; j < 8; j++) {
                int col = bn * 128 + n0 + j;
                int h = col >> 6, e = col & 63;
                C[(((size_t)h * NB + b_) * SEQ + t) * DKV + e] = acc[i][j];
            }
        }
    } else {
#pragma unroll
        for (int i = 0; i < 8; i++) {
            int row = bm * 128 + m0 + i;
            float* Crow = C + (size_t)row * N + bn * 128 + n0;
#pragma unroll
            for (int j = 0; j < 8; j++) {
                float v = acc[i][j];
                if (mode >= 1) v += bias[bn * 128 + n0 + j];
                if (mode == 2) v = fmaxf(v, 0.f);
                Crow[j] = v;
            }
        }
    }
}

// ---------------- fused attention ----------------
// One block per (hb, qtile). smem: QsT[64][68] + KVs[64][68] + Sc[64][520]
#define ATTN_SMEM ((2 * 64 * 68 + 64 * 520) * 4)

__global__ __launch_bounds__(256) void attn_k(
    const float* __restrict__ Q, const float* __restrict__ K, const float* __restrict__ V,
    const int* __restrict__ seq, float* __restrict__ probs, float* __restrict__ Oout,
    int causal, int writeProbs)
{
    extern __shared__ float sm[];
    float* QsT = sm;                 // [e][q] pitch 68
    float* KVs = sm + 64 * 68;       // K as [e][s] pitch 68; V as [s][e] pitch 68
    float* Sc  = sm + 2 * 64 * 68;   // [q][s] pitch 520

    const int hb = blockIdx.y;       // 0..63
    const int qt = blockIdx.x;       // 0..7
    const int h = hb >> 3, b = hb & 7;
    const int tid = threadIdx.x;
    const int tq = tid >> 4, ts = tid & 15;
    const int q0 = tq * 4, s0 = ts * 4;

    // load Q tile transposed
    const float* Qb = Q + ((size_t)hb * SEQ + qt * 64) * DKV;
#pragma unroll
    for (int l = 0; l < 4; l++) {
        int id = tid + l * 256;
        int q = id >> 4, c4 = id & 15;
        float4 v = *(const float4*)(Qb + q * 64 + c4 * 4);
        QsT[(c4 * 4 + 0) * 68 + q] = v.x;
        QsT[(c4 * 4 + 1) * 68 + q] = v.y;
        QsT[(c4 * 4 + 2) * 68 + q] = v.z;
        QsT[(c4 * 4 + 3) * 68 + q] = v.w;
    }

    const float scale = 0.044194173824159216f; // 1/sqrt(512)

    // scores
    for (int st = 0; st < 8; st++) {
        const float* Kb = K + ((size_t)hb * SEQ + st * 64) * DKV;
        __syncthreads();
#pragma unroll
        for (int l = 0; l < 4; l++) {
            int id = tid + l * 256;
            int s = id >> 4, c4 = id & 15;
            float4 v = *(const float4*)(Kb + s * 64 + c4 * 4);
            KVs[(c4 * 4 + 0) * 68 + s] = v.x;
            KVs[(c4 * 4 + 1) * 68 + s] = v.y;
            KVs[(c4 * 4 + 2) * 68 + s] = v.z;
            KVs[(c4 * 4 + 3) * 68 + s] = v.w;
        }
        __syncthreads();
        float acc[4][4];
#pragma unroll
        for (int i = 0; i < 4; i++)
#pragma unroll
            for (int j = 0; j < 4; j++) acc[i][j] = 0.f;
#pragma unroll 8
        for (int e = 0; e < 64; e++) {
            float a[4], kk[4];
#pragma unroll
            for (int i = 0; i < 4; i++) a[i] = QsT[e * 68 + q0 + i];
#pragma unroll
            for (int j = 0; j < 4; j++) kk[j] = KVs[e * 68 + s0 + j];
#pragma unroll
            for (int i = 0; i < 4; i++)
#pragma unroll
                for (int j = 0; j < 4; j++) acc[i][j] = fmaf(a[i], kk[j], acc[i][j]);
        }
#pragma unroll
        for (int i = 0; i < 4; i++) {
            int t = qt * 64 + q0 + i;
#pragma unroll
            for (int j = 0; j < 4; j++) {
                int s = st * 64 + s0 + j;
                float val = acc[i][j] * scale;
                if ((causal && s > t) || seq[b * SEQ + s] == 0) val = -1e30f;
                Sc[(q0 + i) * 520 + s] = val;
            }
        }
    }
    __syncthreads();

    // softmax: each warp handles 8 rows
    {
        const int warp = tid >> 5, lane = tid & 31;
        for (int r = 0; r < 8; r++) {
            int q = warp * 8 + r;
            float* row = Sc + q * 520;
            float mx = -3.0e38f;
            for (int c = lane; c < 512; c += 32) mx = fmaxf(mx, row[c]);
#pragma unroll
            for (int o = 16; o; o >>= 1) mx = fmaxf(mx, __shfl_xor_sync(0xffffffffu, mx, o));
            float sum = 0.f;
            for (int c = lane; c < 512; c += 32) {
                float e = expf(row[c] - mx);
                row[c] = e;
                sum += e;
            }
#pragma unroll
            for (int o = 16; o; o >>= 1) sum += __shfl_xor_sync(0xffffffffu, sum, o);
            float inv = 1.f / sum;
            float* prow = probs + ((size_t)hb * SEQ + qt * 64 + q) * SEQ;
            for (int c = lane; c < 512; c += 32) {
                float p = row[c] * inv;
                row[c] = p;
                if (writeProbs) prow[c] = p;
            }
        }
    }

    // A @ V
    float o[4][4];
#pragma unroll
    for (int i = 0; i < 4; i++)
#pragma unroll
        for (int j = 0; j < 4; j++) o[i][j] = 0.f;

    for (int st = 0; st < 8; st++) {
        const float* Vb = V + ((size_t)hb * SEQ + st * 64) * DKV;
        __syncthreads();
#pragma unroll
        for (int l = 0; l < 4; l++) {
            int id = tid + l * 256;
            int s = id >> 4, c4 = id & 15;
            float4 v = *(const float4*)(Vb + s * 64 + c4 * 4);
            *(float4*)&KVs[s * 68 + c4 * 4] = v;   // natural layout [s][e]
        }
        __syncthreads();
#pragma unroll 4
        for (int s = 0; s < 64; s++) {
            float p[4], vv[4];
#pragma unroll
            for (int i = 0; i < 4; i++) p[i] = Sc[(q0 + i) * 520 + st * 64 + s];
#pragma unroll
            for (int j = 0; j < 4; j++) vv[j] = KVs[s * 68 + s0 + j];
#pragma unroll
            for (int i = 0; i < 4; i++)
#pragma unroll
                for (int j = 0; j < 4; j++) o[i][j] = fmaf(p[i], vv[j], o[i][j]);
        }
    }

#pragma unroll
    for (int i = 0; i < 4; i++) {
        int row = b * SEQ + qt * 64 + q0 + i;
#pragma unroll
        for (int j = 0; j < 4; j++) {
            int col = h * DKV + s0 + j;
            Oout[(size_t)row * DMOD + col] = o[i][j];
        }
    }
}

// ---------------- layernorm(y + res) * g + b -> out ----------------
__global__ __launch_bounds__(128) void ln_k(
    const float* __restrict__ y, const float* __restrict__ res,
    const float* __restrict__ g, const float* __restrict__ b,
    float* __restrict__ out)
{
    __shared__ float red[8];
    int n = blockIdx.x, tid = threadIdx.x;
    int c = tid * 4;
    float4 yv = *(const float4*)(y  + (size_t)n * DMOD + c);
    float4 rv = *(const float4*)(res + (size_t)n * DMOD + c);
    float v0 = yv.x + rv.x, v1 = yv.y + rv.y, v2 = yv.z + rv.z, v3 = yv.w + rv.w;

    float s = v0 + v1 + v2 + v3;
    int lane = tid & 31, warp = tid >> 5;
#pragma unroll
    for (int o = 16; o; o >>= 1) s += __shfl_xor_sync(0xffffffffu, s, o);
    if (lane == 0) red[warp] = s;
    __syncthreads();
    float mu = (red[0] + red[1] + red[2] + red[3]) * (1.f / DMOD);

    float d0 = v0 - mu, d1 = v1 - mu, d2 = v2 - mu, d3 = v3 - mu;
    float ss = d0 * d0 + d1 * d1 + d2 * d2 + d3 * d3;
#pragma unroll
    for (int o = 16; o; o >>= 1) ss += __shfl_xor_sync(0xffffffffu, ss, o);
    if (lane == 0) red[4 + warp] = ss;
    __syncthreads();
    float var = (red[4] + red[5] + red[6] + red[7]) * (1.f / DMOD);
    float is = rsqrtf(var + 1e-5f);

    float4 gv = *(const float4*)(g + c);
    float4 bv = *(const float4*)(b + c);
    float4 ov;
    ov.x = d0 * is * gv.x + bv.x;
    ov.y = d1 * is * gv.y + bv.y;
    ov.z = d2 * is * gv.z + bv.z;
    ov.w = d3 * is * gv.w + bv.w;
    *(float4*)(out + (size_t)n * DMOD + c) = ov;
}

// ---------------- host ----------------
extern "C" void kernel_launch(void* const* d_in, const int* in_sizes, int n_in,
                              void* d_out, int out_size)
{
    const int*   tgt_seq = (const int*)d_in[0];
    const int*   tgt_pos = (const int*)d_in[1];
    const int*   src_seq = (const int*)d_in[2];
    const float* enc_out = (const float*)d_in[3];
    const float* tgt_emb = (const float*)d_in[4];
    const float* pos_emb = (const float*)d_in[5];
    const float* slf_wq  = (const float*)d_in[6];
    const float* slf_wk  = (const float*)d_in[7];
    const float* slf_wv  = (const float*)d_in[8];
    const float* slf_pw  = (const float*)d_in[9];
    const float* slf_pb  = (const float*)d_in[10];
    const float* slf_g   = (const float*)d_in[11];
    const float* slf_b   = (const float*)d_in[12];
    const float* enc_wq  = (const float*)d_in[13];
    const float* enc_wk  = (const float*)d_in[14];
    const float* enc_wv  = (const float*)d_in[15];
    const float* enc_pw  = (const float*)d_in[16];
    const float* enc_pb  = (const float*)d_in[17];
    const float* enc_g   = (const float*)d_in[18];
    const float* enc_b   = (const float*)d_in[19];
    const float* ffn_w1  = (const float*)d_in[20];
    const float* ffn_b1  = (const float*)d_in[21];
    const float* ffn_w2  = (const float*)d_in[22];
    const float* ffn_b2  = (const float*)d_in[23];
    const float* ffn_g   = (const float*)d_in[24];
    const float* ffn_b   = (const float*)d_in[25];

    float *xp, *qp, *kp, *vp, *aop, *yp, *hp, *wrep;
    cudaGetSymbolAddress((void**)&xp,   g_x);
    cudaGetSymbolAddress((void**)&qp,   g_q);
    cudaGetSymbolAddress((void**)&kp,   g_k);
    cudaGetSymbolAddress((void**)&vp,   g_v);
    cudaGetSymbolAddress((void**)&aop,  g_ao);
    cudaGetSymbolAddress((void**)&yp,   g_y);
    cudaGetSymbolAddress((void**)&hp,   g_h);
    cudaGetSymbolAddress((void**)&wrep, g_wrep);

    cudaFuncSetAttribute(attn_k, cudaFuncAttributeMaxDynamicSharedMemorySize, ATTN_SMEM);

    const int full = (out_size >= (int)FULL_OUT) ? 1 : 0;
    float* out_f = (float*)d_out;
    float* probs_slf = out_f + SLF_OFF;
    float* probs_enc = out_f + ENC_OFF;

    // embedding
    embed_k<<<NTOK, 128>>>(tgt_seq, tgt_pos, tgt_emb, pos_emb, xp);

    // repack per-head weights: order per layer: slf q,k,v, enc q,k,v
    for (int l = 0; l < NL; l++) {
        const float* srcs[6] = {
            slf_wq + (size_t)l * NH * DMOD * DKV,
            slf_wk + (size_t)l * NH * DMOD * DKV,
            slf_wv + (size_t)l * NH * DMOD * DKV,
            enc_wq + (size_t)l * NH * DMOD * DKV,
            enc_wk + (size_t)l * NH * DMOD * DKV,
            enc_wv + (size_t)l * NH * DMOD * DKV,
        };
        for (int j = 0; j < 6; j++)
            repack_k<<<1024, 256>>>(srcs[j], wrep + ((size_t)l * 6 + j) * DMOD * DMOD);
    }

    dim3 gN512(512 / 128, NTOK / 128);   // (4, 32)
    dim3 gN2048(2048 / 128, NTOK / 128); // (16, 32)
    dim3 gAttn(8, NHB);

    for (int l = 0; l < NL; l++) {
        const float* wq = wrep + ((size_t)l * 6 + 0) * DMOD * DMOD;
        const float* wk = wrep + ((size_t)l * 6 + 1) * DMOD * DMOD;
        const float* wv = wrep + ((size_t)l * 6 + 2) * DMOD * DMOD;
        const float* ewq = wrep + ((size_t)l * 6 + 3) * DMOD * DMOD;
        const float* ewk = wrep + ((size_t)l * 6 + 4) * DMOD * DMOD;
        const float* ewv = wrep + ((size_t)l * 6 + 5) * DMOD * DMOD;

        // ---- self attention ----
        sgemm_k<<<gN512, 256>>>(xp, wq, nullptr, qp, NTOK, DMOD, DMOD, 3);
        sgemm_k<<<gN512, 256>>>(xp, wk, nullptr, kp, NTOK, DMOD, DMOD, 3);
        sgemm_k<<<gN512, 256>>>(xp, wv, nullptr, vp, NTOK, DMOD, DMOD, 3);
        attn_k<<<gAttn, 256, ATTN_SMEM>>>(qp, kp, vp, tgt_seq,
                                          probs_slf + (size_t)l * ATT_PER_L, aop, 1, full);
        sgemm_k<<<gN512, 256>>>(aop, slf_pw + (size_t)l * DMOD * DMOD,
                                slf_pb + (size_t)l * DMOD, yp, NTOK, DMOD, DMOD, 1);
        ln_k<<<NTOK, 128>>>(yp, xp, slf_g + (size_t)l * DMOD, slf_b + (size_t)l * DMOD, xp);

        // ---- cross attention ----
        sgemm_k<<<gN512, 256>>>(xp,      ewq, nullptr, qp, NTOK, DMOD, DMOD, 3);
        sgemm_k<<<gN512, 256>>>(enc_out, ewk, nullptr, kp, NTOK, DMOD, DMOD, 3);
        sgemm_k<<<gN512, 256>>>(enc_out, ewv, nullptr, vp, NTOK, DMOD, DMOD, 3);
        attn_k<<<gAttn, 256, ATTN_SMEM>>>(qp, kp, vp, src_seq,
                                          probs_enc + (size_t)l * ATT_PER_L, aop, 0, full);
        sgemm_k<<<gN512, 256>>>(aop, enc_pw + (size_t)l * DMOD * DMOD,
                                enc_pb + (size_t)l * DMOD, yp, NTOK, DMOD, DMOD, 1);
        ln_k<<<NTOK, 128>>>(yp, xp, enc_g + (size_t)l * DMOD, enc_b + (size_t)l * DMOD, xp);

        // ---- FFN ----
        sgemm_k<<<gN2048, 256>>>(xp, ffn_w1 + (size_t)l * DMOD * DFF,
                                 ffn_b1 + (size_t)l * DFF, hp, NTOK, DFF, DMOD, 2);
        sgemm_k<<<gN512, 256>>>(hp, ffn_w2 + (size_t)l * DFF * DMOD,
                                ffn_b2 + (size_t)l * DMOD, yp, NTOK, DMOD, DFF, 1);
        ln_k<<<NTOK, 128>>>(yp, xp, ffn_g + (size_t)l * DMOD, ffn_b + (size_t)l * DMOD, xp);
    }

    // final x -> d_out[0 : X_ELEMS]
    size_t copy_elems = (size_t)out_size < (size_t)X_ELEMS ? (size_t)out_size : (size_t)X_ELEMS;
    cudaMemcpyAsync(d_out, xp, copy_elems * sizeof(float), cudaMemcpyDeviceToDevice);
}

// round 6
// speedup vs baseline: 1.6947x; 1.6947x over previous
#include <cuda_runtime.h>
#include <cuda_bf16.h>
#include <cstdint>

// Problem constants
#define NL   6
#define NH   8
#define DMOD 512
#define DKV  64
#define DFF  2048
#define NB   8
#define SEQ  512
#define NTOK 4096          // NB*SEQ
#define NHB  64            // NH*NB

#define X_ELEMS   (NTOK*DMOD)                 // 2,097,152
#define ATT_PER_L ((size_t)NHB*SEQ*SEQ)       // 16,777,216
#define SLF_OFF   ((size_t)X_ELEMS)
#define ENC_OFF   (SLF_OFF + (size_t)NL*ATT_PER_L)
#define FULL_OUT  (ENC_OFF + (size_t)NL*ATT_PER_L)   // 203,423,744

// per-layer bf16 weight bank layout (element offsets)
#define WOFF_SQ   0
#define WOFF_SK   262144
#define WOFF_SV   524288
#define WOFF_SPW  786432
#define WOFF_EQ   1048576
#define WOFF_EK   1310720
#define WOFF_EV   1572864
#define WOFF_EPW  1835008
#define WOFF_W1   2097152
#define WOFF_W2   3145728
#define WL_SIZE   4194304

// ---------------- scratch (no allocations allowed) ----------------
__device__ float g_x  [NTOK*DMOD];
__device__ float g_y  [NTOK*DMOD];
__device__ float g_qkv[3*NHB*SEQ*DKV];          // q | k | v, each 2,097,152
__device__ __nv_bfloat16 g_xhi [NTOK*DMOD];
__device__ __nv_bfloat16 g_xlo [NTOK*DMOD];
__device__ __nv_bfloat16 g_ehi [NTOK*DMOD];
__device__ __nv_bfloat16 g_elo [NTOK*DMOD];
__device__ __nv_bfloat16 g_aohi[NTOK*DMOD];
__device__ __nv_bfloat16 g_aolo[NTOK*DMOD];
__device__ __nv_bfloat16 g_hhi [NTOK*DFF];
__device__ __nv_bfloat16 g_hlo [NTOK*DFF];
__device__ __nv_bfloat16 g_wbhi[(size_t)NL*WL_SIZE];
__device__ __nv_bfloat16 g_wblo[(size_t)NL*WL_SIZE];

// ---------------- helpers (baseline PTX only: sm_80-class) ----------------
__device__ __forceinline__ uint32_t smem_u32(const void* p) {
    uint32_t a;
    asm("{ .reg .u64 t; cvta.to.shared.u64 t, %1; cvt.u32.u64 %0, t; }" : "=r"(a) : "l"(p));
    return a;
}
__device__ __forceinline__ void cp16(uint32_t saddr, const void* g) {
    asm volatile("cp.async.cg.shared.global [%0], [%1], 16;" :: "r"(saddr), "l"(g));
}
#define CP_COMMIT() asm volatile("cp.async.commit_group;" ::: "memory")
#define CP_WAIT1()  asm volatile("cp.async.wait_group 1;" ::: "memory")
#define CP_WAIT0()  asm volatile("cp.async.wait_group 0;" ::: "memory")

__device__ __forceinline__ void ldsm_x4(uint32_t* r, uint32_t addr) {
    asm volatile("ldmatrix.sync.aligned.m8n8.x4.shared.b16 {%0,%1,%2,%3}, [%4];"
                 : "=r"(r[0]), "=r"(r[1]), "=r"(r[2]), "=r"(r[3]) : "r"(addr));
}
__device__ __forceinline__ void mma16816(float* d, const uint32_t* a, const uint32_t* b) {
    asm volatile("mma.sync.aligned.m16n8k16.row.col.f32.bf16.bf16.f32 "
                 "{%0,%1,%2,%3}, {%4,%5,%6,%7}, {%8,%9}, {%0,%1,%2,%3};"
                 : "+f"(d[0]), "+f"(d[1]), "+f"(d[2]), "+f"(d[3])
                 : "r"(a[0]), "r"(a[1]), "r"(a[2]), "r"(a[3]), "r"(b[0]), "r"(b[1]));
}

__device__ __forceinline__ void fsplit(float v, __nv_bfloat16& h, __nv_bfloat16& l) {
    h = __float2bfloat16(v);
    l = __float2bfloat16(v - __bfloat162float(h));
}

// ---------------- embedding (fp32 x + bf16 hi/lo) ----------------
__global__ void embed_k(const int* __restrict__ seq, const int* __restrict__ pos,
                        const float* __restrict__ wemb, const float* __restrict__ pemb,
                        float* __restrict__ x,
                        __nv_bfloat16* __restrict__ xhi, __nv_bfloat16* __restrict__ xlo) {
    int n = blockIdx.x;
    int s = seq[n], p = pos[n];
    const float* we = wemb + (size_t)s * DMOD;
    const float* pe = pemb + (size_t)p * DMOD;
    for (int c = threadIdx.x; c < DMOD; c += blockDim.x) {
        float v = we[c] + pe[c];
        x[(size_t)n * DMOD + c] = v;
        __nv_bfloat16 h, l; fsplit(v, h, l);
        xhi[(size_t)n * DMOD + c] = h;
        xlo[(size_t)n * DMOD + c] = l;
    }
}

// ---------------- fp32 -> bf16 hi/lo split (for enc_output) ----------------
__global__ void conv_split_k(const float* __restrict__ src,
                             __nv_bfloat16* __restrict__ hi, __nv_bfloat16* __restrict__ lo,
                             int n) {
    int i = blockIdx.x * blockDim.x + threadIdx.x;
    if (i < n) {
        __nv_bfloat16 h, l; fsplit(src[i], h, l);
        hi[i] = h; lo[i] = l;
    }
}

// ---------------- qkv weight repack: [H,D,DK] fp32 -> B[n=h*64+e][k=d] bf16 hi/lo ----------------
__global__ void qkv_repack_tc(const float* __restrict__ src,
                              __nv_bfloat16* __restrict__ dhi, __nv_bfloat16* __restrict__ dlo) {
    __shared__ float t[64][65];
    int h = blockIdx.x >> 3, dt = blockIdx.x & 7;
    int d0 = dt * 64;
    int tid = threadIdx.x;
    for (int i = tid; i < 4096; i += 256) {
        int d = i >> 6, e = i & 63;
        t[e][d] = src[h * (DMOD * DKV) + (d0 + d) * DKV + e];
    }
    __syncthreads();
    for (int i = tid; i < 4096; i += 256) {
        int e = i >> 6, d = i & 63;
        __nv_bfloat16 hh, ll; fsplit(t[e][d], hh, ll);
        size_t o = (size_t)(h * 64 + e) * DMOD + d0 + d;
        dhi[o] = hh; dlo[o] = ll;
    }
}

// ---------------- generic transpose+split: src fp32 [R,C] -> dst bf16 [C,R] ----------------
__global__ void trans_conv_k(const float* __restrict__ src,
                             __nv_bfloat16* __restrict__ dhi, __nv_bfloat16* __restrict__ dlo,
                             int R, int C) {
    __shared__ float t[32][33];
    int c0 = blockIdx.x * 32, r0 = blockIdx.y * 32;
    int x = threadIdx.x, y = threadIdx.y;        // 32 x 8
    for (int yy = y; yy < 32; yy += 8)
        t[yy][x] = src[(size_t)(r0 + yy) * C + c0 + x];
    __syncthreads();
    for (int yy = y; yy < 32; yy += 8) {
        __nv_bfloat16 hh, ll; fsplit(t[x][yy], hh, ll);
        size_t o = (size_t)(c0 + yy) * R + r0 + x;
        dhi[o] = hh; dlo[o] = ll;
    }
}

// ---------------- mma.sync bf16-split GEMM: C[M,N] = A[M,K] @ B[N,K]^T ----------------
// 3 passes: Ahi*Bhi + Ahi*Blo + Alo*Bhi, fp32 register accumulators.
// mode 1: +bias -> fp32 Cf;  mode 2: +bias,relu -> bf16 Chi/Clo;  mode 3: qkv scatter.
#define GM_PITCH 40                  // bf16 elems per smem row (80B, conflict-free ldmatrix)
#define GM_TILEB (128*GM_PITCH*2)    // 10240 B per 128x32 tile
#define GM_STAGE (4*GM_TILEB)        // Ahi|Alo|Bhi|Blo = 40960 B
#define GM_SMEM  (2*GM_STAGE)        // 81920 B double buffered

__global__ __launch_bounds__(256, 1) void gemm_mma_k(
    const __nv_bfloat16* __restrict__ Ahi, const __nv_bfloat16* __restrict__ Alo,
    const __nv_bfloat16* __restrict__ Bhi, const __nv_bfloat16* __restrict__ Blo,
    const float* __restrict__ bias,
    float* __restrict__ Cf,
    __nv_bfloat16* __restrict__ Chi, __nv_bfloat16* __restrict__ Clo,
    int M, int N, int K, int mode)
{
    extern __shared__ __align__(16) char smem[];
    uint32_t sb = smem_u32(smem);
    const int tid = threadIdx.x, lane = tid & 31, w = tid >> 5;
    const int wm = w >> 2, wn = w & 3;          // warp grid 2 x 4 -> 64 x 32 tiles
    const int n0 = blockIdx.x * 128, m0 = blockIdx.y * 128;

    const __nv_bfloat16* srcs[4] = {
        Ahi + (size_t)m0 * K, Alo + (size_t)m0 * K,
        Bhi + (size_t)n0 * K, Blo + (size_t)n0 * K };

    // per-thread load slots: 2 segs of 16B per tile
    const int seg0 = tid * 2;
    const int lrow = seg0 >> 2, lc = seg0 & 3;

    auto load_chunk = [&](int kc, int st) {
        const int k0 = kc * 32;
        uint32_t stb = sb + st * GM_STAGE;
#pragma unroll
        for (int t = 0; t < 4; t++) {
            const __nv_bfloat16* src = srcs[t] + k0 + (size_t)lrow * K + lc * 8;
            uint32_t tb = stb + t * GM_TILEB + (lrow * GM_PITCH + lc * 8) * 2;
            cp16(tb, src);
            cp16(tb + 16, src + 8);
        }
    };

    float acc[4][4][4];
#pragma unroll
    for (int a = 0; a < 4; a++)
#pragma unroll
        for (int b = 0; b < 4; b++)
#pragma unroll
            for (int c = 0; c < 4; c++) acc[a][b][c] = 0.f;

    const int nch = K >> 5;
    load_chunk(0, 0); CP_COMMIT();

    // fragment smem addresses (per lane, stage-relative)
    const uint32_t a_off = ((wm * 64 + (lane & 15)) * GM_PITCH + ((lane >> 4) << 3)) * 2;
    const uint32_t b_off = (((wn * 32) + ((lane & 16) ? 8 : 0) + (lane & 7)) * GM_PITCH
                            + ((lane & 8) ? 8 : 0)) * 2;

    for (int kc = 0; kc < nch; kc++) {
        if (kc + 1 < nch) { load_chunk(kc + 1, (kc + 1) & 1); CP_COMMIT(); CP_WAIT1(); }
        else { CP_WAIT0(); }
        __syncthreads();

        uint32_t stb = sb + (kc & 1) * GM_STAGE;
#pragma unroll
        for (int ks = 0; ks < 2; ks++) {
            uint32_t ah[4][4], al[4][4], bh[2][4], bl[2][4];
            const uint32_t kso = ks * 32;   // 16 elems * 2B
#pragma unroll
            for (int mi = 0; mi < 4; mi++) {
                uint32_t off = a_off + mi * 16 * GM_PITCH * 2 + kso;
                ldsm_x4(ah[mi], stb + 0 * GM_TILEB + off);
                ldsm_x4(al[mi], stb + 1 * GM_TILEB + off);
            }
#pragma unroll
            for (int bi = 0; bi < 2; bi++) {
                uint32_t off = b_off + bi * 16 * GM_PITCH * 2 + kso;
                ldsm_x4(bh[bi], stb + 2 * GM_TILEB + off);
                ldsm_x4(bl[bi], stb + 3 * GM_TILEB + off);
            }
#pragma unroll
            for (int mi = 0; mi < 4; mi++)
#pragma unroll
                for (int ni = 0; ni < 4; ni++) {
                    const uint32_t* bhf = &bh[ni >> 1][(ni & 1) * 2];
                    const uint32_t* blf = &bl[ni >> 1][(ni & 1) * 2];
                    mma16816(acc[mi][ni], ah[mi], bhf);
                    mma16816(acc[mi][ni], ah[mi], blf);
                    mma16816(acc[mi][ni], al[mi], bhf);
                }
        }
        __syncthreads();
    }

    // epilogue
#pragma unroll
    for (int mi = 0; mi < 4; mi++) {
        int r0 = m0 + wm * 64 + mi * 16 + (lane >> 2);
#pragma unroll
        for (int ni = 0; ni < 4; ni++) {
            int col = n0 + wn * 32 + ni * 8 + (lane & 3) * 2;
            float c0 = acc[mi][ni][0], c1 = acc[mi][ni][1];
            float c2 = acc[mi][ni][2], c3 = acc[mi][ni][3];
            if (mode == 3) {
                int m = col >> 9, h = (col >> 6) & 7, e = col & 63;
#pragma unroll
                for (int rr = 0; rr < 2; rr++) {
                    int row = r0 + rr * 8;
                    int b_ = row >> 9, t = row & 511;
                    float2 v; v.x = rr ? c2 : c0; v.y = rr ? c3 : c1;
                    *(float2*)(Cf + (size_t)m * 2097152 +
                               (((size_t)(h * NB + b_) * SEQ + t) * DKV + e)) = v;
                }
            } else if (mode == 1) {
                float2 bv = *(const float2*)(bias + col);
                float2 v0; v0.x = c0 + bv.x; v0.y = c1 + bv.y;
                float2 v1; v1.x = c2 + bv.x; v1.y = c3 + bv.y;
                *(float2*)(Cf + (size_t)r0 * N + col)       = v0;
                *(float2*)(Cf + (size_t)(r0 + 8) * N + col) = v1;
            } else {
                float2 bv = *(const float2*)(bias + col);
                float p0 = fmaxf(c0 + bv.x, 0.f), p1 = fmaxf(c1 + bv.y, 0.f);
                float p2 = fmaxf(c2 + bv.x, 0.f), p3 = fmaxf(c3 + bv.y, 0.f);
                __nv_bfloat16 h0, l0, h1, l1, h2, l2, h3, l3;
                fsplit(p0, h0, l0); fsplit(p1, h1, l1);
                fsplit(p2, h2, l2); fsplit(p3, h3, l3);
                __nv_bfloat162 ph0; ph0.x = h0; ph0.y = h1;
                __nv_bfloat162 ph1; ph1.x = h2; ph1.y = h3;
                __nv_bfloat162 pl0; pl0.x = l0; pl0.y = l1;
                __nv_bfloat162 pl1; pl1.x = l2; pl1.y = l3;
                *(__nv_bfloat162*)(Chi + (size_t)r0 * N + col)       = ph0;
                *(__nv_bfloat162*)(Chi + (size_t)(r0 + 8) * N + col) = ph1;
                *(__nv_bfloat162*)(Clo + (size_t)r0 * N + col)       = pl0;
                *(__nv_bfloat162*)(Clo + (size_t)(r0 + 8) * N + col) = pl1;
            }
        }
    }
}

// ---------------- fused attention (fp32 FFMA; bf16 hi/lo output) ----------------
#define ATTN_SMEM ((2 * 64 * 68 + 64 * 520) * 4)

__global__ __launch_bounds__(256) void attn_k(
    const float* __restrict__ Q, const float* __restrict__ K, const float* __restrict__ V,
    const int* __restrict__ seq, float* __restrict__ probs,
    __nv_bfloat16* __restrict__ Ohi, __nv_bfloat16* __restrict__ Olo,
    int causal, int writeProbs)
{
    extern __shared__ float sm[];
    float* QsT = sm;                 // [e][q] pitch 68
    float* KVs = sm + 64 * 68;       // K as [e][s] pitch 68; V as [s][e] pitch 68
    float* Sc  = sm + 2 * 64 * 68;   // [q][s] pitch 520

    const int hb = blockIdx.y;
    const int qt = blockIdx.x;
    const int h = hb >> 3, b = hb & 7;
    const int tid = threadIdx.x;
    const int tq = tid >> 4, ts = tid & 15;
    const int q0 = tq * 4, s0 = ts * 4;

    const float* Qb = Q + ((size_t)hb * SEQ + qt * 64) * DKV;
#pragma unroll
    for (int l = 0; l < 4; l++) {
        int id = tid + l * 256;
        int q = id >> 4, c4 = id & 15;
        float4 v = *(const float4*)(Qb + q * 64 + c4 * 4);
        QsT[(c4 * 4 + 0) * 68 + q] = v.x;
        QsT[(c4 * 4 + 1) * 68 + q] = v.y;
        QsT[(c4 * 4 + 2) * 68 + q] = v.z;
        QsT[(c4 * 4 + 3) * 68 + q] = v.w;
    }

    const float scale = 0.044194173824159216f;

    for (int st = 0; st < 8; st++) {
        const float* Kb = K + ((size_t)hb * SEQ + st * 64) * DKV;
        __syncthreads();
#pragma unroll
        for (int l = 0; l < 4; l++) {
            int id = tid + l * 256;
            int s = id >> 4, c4 = id & 15;
            float4 v = *(const float4*)(Kb + s * 64 + c4 * 4);
            KVs[(c4 * 4 + 0) * 68 + s] = v.x;
            KVs[(c4 * 4 + 1) * 68 + s] = v.y;
            KVs[(c4 * 4 + 2) * 68 + s] = v.z;
            KVs[(c4 * 4 + 3) * 68 + s] = v.w;
        }
        __syncthreads();
        float acc[4][4];
#pragma unroll
        for (int i = 0; i < 4; i++)
#pragma unroll
            for (int j = 0; j < 4; j++) acc[i][j] = 0.f;
#pragma unroll 8
        for (int e = 0; e < 64; e++) {
            float4 a4 = *(const float4*)&QsT[e * 68 + q0];
            float4 k4 = *(const float4*)&KVs[e * 68 + s0];
            float a[4] = {a4.x, a4.y, a4.z, a4.w};
            float kk[4] = {k4.x, k4.y, k4.z, k4.w};
#pragma unroll
            for (int i = 0; i < 4; i++)
#pragma unroll
                for (int j = 0; j < 4; j++) acc[i][j] = fmaf(a[i], kk[j], acc[i][j]);
        }
#pragma unroll
        for (int i = 0; i < 4; i++) {
            int t = qt * 64 + q0 + i;
#pragma unroll
            for (int j = 0; j < 4; j++) {
                int s = st * 64 + s0 + j;
                float val = acc[i][j] * scale;
                if ((causal && s > t) || seq[b * SEQ + s] == 0) val = -1e30f;
                Sc[(q0 + i) * 520 + s] = val;
            }
        }
    }
    __syncthreads();

    {
        const int warp = tid >> 5, lane = tid & 31;
        for (int r = 0; r < 8; r++) {
            int q = warp * 8 + r;
            float* row = Sc + q * 520;
            float mx = -3.0e38f;
            for (int c = lane; c < 512; c += 32) mx = fmaxf(mx, row[c]);
#pragma unroll
            for (int o = 16; o; o >>= 1) mx = fmaxf(mx, __shfl_xor_sync(0xffffffffu, mx, o));
            float sum = 0.f;
            for (int c = lane; c < 512; c += 32) {
                float e = __expf(row[c] - mx);
                row[c] = e;
                sum += e;
            }
#pragma unroll
            for (int o = 16; o; o >>= 1) sum += __shfl_xor_sync(0xffffffffu, sum, o);
            float inv = 1.f / sum;
            float* prow = probs + ((size_t)hb * SEQ + qt * 64 + q) * SEQ;
            for (int c = lane; c < 512; c += 32) {
                float p = row[c] * inv;
                row[c] = p;
                if (writeProbs) prow[c] = p;
            }
        }
    }

    float o[4][4];
#pragma unroll
    for (int i = 0; i < 4; i++)
#pragma unroll
        for (int j = 0; j < 4; j++) o[i][j] = 0.f;

    for (int st = 0; st < 8; st++) {
        const float* Vb = V + ((size_t)hb * SEQ + st * 64) * DKV;
        __syncthreads();
#pragma unroll
        for (int l = 0; l < 4; l++) {
            int id = tid + l * 256;
            int s = id >> 4, c4 = id & 15;
            float4 v = *(const float4*)(Vb + s * 64 + c4 * 4);
            *(float4*)&KVs[s * 68 + c4 * 4] = v;
        }
        __syncthreads();
#pragma unroll 4
        for (int s = 0; s < 64; s++) {
            float p[4];
#pragma unroll
            for (int i = 0; i < 4; i++) p[i] = Sc[(q0 + i) * 520 + st * 64 + s];
            float4 v4 = *(const float4*)&KVs[s * 68 + s0];
            float vv[4] = {v4.x, v4.y, v4.z, v4.w};
#pragma unroll
            for (int i = 0; i < 4; i++)
#pragma unroll
                for (int j = 0; j < 4; j++) o[i][j] = fmaf(p[i], vv[j], o[i][j]);
        }
    }

#pragma unroll
    for (int i = 0; i < 4; i++) {
        int row = b * SEQ + qt * 64 + q0 + i;
        int col = h * DKV + s0;
        __nv_bfloat16 h0, l0, h1, l1, h2, l2, h3, l3;
        fsplit(o[i][0], h0, l0); fsplit(o[i][1], h1, l1);
        fsplit(o[i][2], h2, l2); fsplit(o[i][3], h3, l3);
        __nv_bfloat162 ph0; ph0.x = h0; ph0.y = h1;
        __nv_bfloat162 ph1; ph1.x = h2; ph1.y = h3;
        __nv_bfloat162 pl0; pl0.x = l0; pl0.y = l1;
        __nv_bfloat162 pl1; pl1.x = l2; pl1.y = l3;
        *(__nv_bfloat162*)(Ohi + (size_t)row * DMOD + col)     = ph0;
        *(__nv_bfloat162*)(Ohi + (size_t)row * DMOD + col + 2) = ph1;
        *(__nv_bfloat162*)(Olo + (size_t)row * DMOD + col)     = pl0;
        *(__nv_bfloat162*)(Olo + (size_t)row * DMOD + col + 2) = pl1;
    }
}

// ---------------- layernorm(y + res) -> fp32 out + bf16 hi/lo ----------------
__global__ __launch_bounds__(128) void ln_k(
    const float* __restrict__ y, const float* __restrict__ res,
    const float* __restrict__ g, const float* __restrict__ b,
    float* __restrict__ out,
    __nv_bfloat16* __restrict__ ohi, __nv_bfloat16* __restrict__ olo)
{
    __shared__ float red[8];
    int n = blockIdx.x, tid = threadIdx.x;
    int c = tid * 4;
    float4 yv = *(const float4*)(y   + (size_t)n * DMOD + c);
    float4 rv = *(const float4*)(res + (size_t)n * DMOD + c);
    float v0 = yv.x + rv.x, v1 = yv.y + rv.y, v2 = yv.z + rv.z, v3 = yv.w + rv.w;

    float s = v0 + v1 + v2 + v3;
    int lane = tid & 31, warp = tid >> 5;
#pragma unroll
    for (int o = 16; o; o >>= 1) s += __shfl_xor_sync(0xffffffffu, s, o);
    if (lane == 0) red[warp] = s;
    __syncthreads();
    float mu = (red[0] + red[1] + red[2] + red[3]) * (1.f / DMOD);

    float d0 = v0 - mu, d1 = v1 - mu, d2 = v2 - mu, d3 = v3 - mu;
    float ss = d0 * d0 + d1 * d1 + d2 * d2 + d3 * d3;
#pragma unroll
    for (int o = 16; o; o >>= 1) ss += __shfl_xor_sync(0xffffffffu, ss, o);
    if (lane == 0) red[4 + warp] = ss;
    __syncthreads();
    float var = (red[4] + red[5] + red[6] + red[7]) * (1.f / DMOD);
    float is = rsqrtf(var + 1e-5f);

    float4 gv = *(const float4*)(g + c);
    float4 bv = *(const float4*)(b + c);
    float4 ov;
    ov.x = d0 * is * gv.x + bv.x;
    ov.y = d1 * is * gv.y + bv.y;
    ov.z = d2 * is * gv.z + bv.z;
    ov.w = d3 * is * gv.w + bv.w;
    *(float4*)(out + (size_t)n * DMOD + c) = ov;

    __nv_bfloat16 h0, l0, h1, l1, h2, l2, h3, l3;
    fsplit(ov.x, h0, l0); fsplit(ov.y, h1, l1);
    fsplit(ov.z, h2, l2); fsplit(ov.w, h3, l3);
    __nv_bfloat162 ph0; ph0.x = h0; ph0.y = h1;
    __nv_bfloat162 ph1; ph1.x = h2; ph1.y = h3;
    __nv_bfloat162 pl0; pl0.x = l0; pl0.y = l1;
    __nv_bfloat162 pl1; pl1.x = l2; pl1.y = l3;
    *(__nv_bfloat162*)(ohi + (size_t)n * DMOD + c)     = ph0;
    *(__nv_bfloat162*)(ohi + (size_t)n * DMOD + c + 2) = ph1;
    *(__nv_bfloat162*)(olo + (size_t)n * DMOD + c)     = pl0;
    *(__nv_bfloat162*)(olo + (size_t)n * DMOD + c + 2) = pl1;
}

// ---------------- host ----------------
extern "C" void kernel_launch(void* const* d_in, const int* in_sizes, int n_in,
                              void* d_out, int out_size)
{
    const int*   tgt_seq = (const int*)d_in[0];
    const int*   tgt_pos = (const int*)d_in[1];
    const int*   src_seq = (const int*)d_in[2];
    const float* enc_out = (const float*)d_in[3];
    const float* tgt_emb = (const float*)d_in[4];
    const float* pos_emb = (const float*)d_in[5];
    const float* slf_wq  = (const float*)d_in[6];
    const float* slf_wk  = (const float*)d_in[7];
    const float* slf_wv  = (const float*)d_in[8];
    const float* slf_pw  = (const float*)d_in[9];
    const float* slf_pb  = (const float*)d_in[10];
    const float* slf_g   = (const float*)d_in[11];
    const float* slf_b   = (const float*)d_in[12];
    const float* enc_wq  = (const float*)d_in[13];
    const float* enc_wk  = (const float*)d_in[14];
    const float* enc_wv  = (const float*)d_in[15];
    const float* enc_pw  = (const float*)d_in[16];
    const float* enc_pb  = (const float*)d_in[17];
    const float* enc_g   = (const float*)d_in[18];
    const float* enc_b   = (const float*)d_in[19];
    const float* ffn_w1  = (const float*)d_in[20];
    const float* ffn_b1  = (const float*)d_in[21];
    const float* ffn_w2  = (const float*)d_in[22];
    const float* ffn_b2  = (const float*)d_in[23];
    const float* ffn_g   = (const float*)d_in[24];
    const float* ffn_b   = (const float*)d_in[25];

    float *xp, *yp, *qkv;
    __nv_bfloat16 *xhi, *xlo, *ehi, *elo, *aohi, *aolo, *hhi, *hlo, *wbhi, *wblo;
    cudaGetSymbolAddress((void**)&xp,   g_x);
    cudaGetSymbolAddress((void**)&yp,   g_y);
    cudaGetSymbolAddress((void**)&qkv,  g_qkv);
    cudaGetSymbolAddress((void**)&xhi,  g_xhi);
    cudaGetSymbolAddress((void**)&xlo,  g_xlo);
    cudaGetSymbolAddress((void**)&ehi,  g_ehi);
    cudaGetSymbolAddress((void**)&elo,  g_elo);
    cudaGetSymbolAddress((void**)&aohi, g_aohi);
    cudaGetSymbolAddress((void**)&aolo, g_aolo);
    cudaGetSymbolAddress((void**)&hhi,  g_hhi);
    cudaGetSymbolAddress((void**)&hlo,  g_hlo);
    cudaGetSymbolAddress((void**)&wbhi, g_wbhi);
    cudaGetSymbolAddress((void**)&wblo, g_wblo);

    cudaFuncSetAttribute(attn_k,     cudaFuncAttributeMaxDynamicSharedMemorySize, ATTN_SMEM);
    cudaFuncSetAttribute(gemm_mma_k, cudaFuncAttributeMaxDynamicSharedMemorySize, GM_SMEM);

    const int full = (out_size >= (int)FULL_OUT) ? 1 : 0;
    float* out_f = (float*)d_out;
    float* probs_slf = out_f + SLF_OFF;
    float* probs_enc = out_f + ENC_OFF;

    float* qp = qkv;
    float* kp = qkv + 2097152;
    float* vp = qkv + 4194304;

    // embedding (+ bf16 split) and enc_output split
    embed_k<<<NTOK, 128>>>(tgt_seq, tgt_pos, tgt_emb, pos_emb, xp, xhi, xlo);
    conv_split_k<<<(NTOK * DMOD) / 256, 256>>>(enc_out, ehi, elo, NTOK * DMOD);

    // weight prep: bf16 hi/lo, transposed to [N,K]
    for (int l = 0; l < NL; l++) {
        size_t LB = (size_t)l * WL_SIZE;
        size_t wsz = (size_t)NH * DMOD * DKV;
        qkv_repack_tc<<<64, 256>>>(slf_wq + l * wsz, wbhi + LB + WOFF_SQ, wblo + LB + WOFF_SQ);
        qkv_repack_tc<<<64, 256>>>(slf_wk + l * wsz, wbhi + LB + WOFF_SK, wblo + LB + WOFF_SK);
        qkv_repack_tc<<<64, 256>>>(slf_wv + l * wsz, wbhi + LB + WOFF_SV, wblo + LB + WOFF_SV);
        qkv_repack_tc<<<64, 256>>>(enc_wq + l * wsz, wbhi + LB + WOFF_EQ, wblo + LB + WOFF_EQ);
        qkv_repack_tc<<<64, 256>>>(enc_wk + l * wsz, wbhi + LB + WOFF_EK, wblo + LB + WOFF_EK);
        qkv_repack_tc<<<64, 256>>>(enc_wv + l * wsz, wbhi + LB + WOFF_EV, wblo + LB + WOFF_EV);
        trans_conv_k<<<dim3(16, 16), dim3(32, 8)>>>(slf_pw + (size_t)l * DMOD * DMOD,
            wbhi + LB + WOFF_SPW, wblo + LB + WOFF_SPW, DMOD, DMOD);
        trans_conv_k<<<dim3(16, 16), dim3(32, 8)>>>(enc_pw + (size_t)l * DMOD * DMOD,
            wbhi + LB + WOFF_EPW, wblo + LB + WOFF_EPW, DMOD, DMOD);
        trans_conv_k<<<dim3(64, 16), dim3(32, 8)>>>(ffn_w1 + (size_t)l * DMOD * DFF,
            wbhi + LB + WOFF_W1, wblo + LB + WOFF_W1, DMOD, DFF);
        trans_conv_k<<<dim3(16, 64), dim3(32, 8)>>>(ffn_w2 + (size_t)l * DFF * DMOD,
            wbhi + LB + WOFF_W2, wblo + LB + WOFF_W2, DFF, DMOD);
    }

    dim3 gAttn(8, NHB);

    for (int l = 0; l < NL; l++) {
        size_t LB = (size_t)l * WL_SIZE;

        // ---- self attention: fused QKV (N=1536) ----
        gemm_mma_k<<<dim3(12, 32), 256, GM_SMEM>>>(xhi, xlo,
            wbhi + LB + WOFF_SQ, wblo + LB + WOFF_SQ,
            nullptr, qkv, nullptr, nullptr, NTOK, 1536, DMOD, 3);
        attn_k<<<gAttn, 256, ATTN_SMEM>>>(qp, kp, vp, tgt_seq,
            probs_slf + (size_t)l * ATT_PER_L, aohi, aolo, 1, full);
        gemm_mma_k<<<dim3(4, 32), 256, GM_SMEM>>>(aohi, aolo,
            wbhi + LB + WOFF_SPW, wblo + LB + WOFF_SPW,
            slf_pb + (size_t)l * DMOD, yp, nullptr, nullptr, NTOK, DMOD, DMOD, 1);
        ln_k<<<NTOK, 128>>>(yp, xp, slf_g + (size_t)l * DMOD, slf_b + (size_t)l * DMOD,
                            xp, xhi, xlo);

        // ---- cross attention: Q from x (N=512), fused KV from enc (N=1024) ----
        gemm_mma_k<<<dim3(4, 32), 256, GM_SMEM>>>(xhi, xlo,
            wbhi + LB + WOFF_EQ, wblo + LB + WOFF_EQ,
            nullptr, qkv, nullptr, nullptr, NTOK, DMOD, DMOD, 3);
        gemm_mma_k<<<dim3(8, 32), 256, GM_SMEM>>>(ehi, elo,
            wbhi + LB + WOFF_EK, wblo + LB + WOFF_EK,
            nullptr, qkv + 2097152, nullptr, nullptr, NTOK, 1024, DMOD, 3);
        attn_k<<<gAttn, 256, ATTN_SMEM>>>(qp, kp, vp, src_seq,
            probs_enc + (size_t)l * ATT_PER_L, aohi, aolo, 0, full);
        gemm_mma_k<<<dim3(4, 32), 256, GM_SMEM>>>(aohi, aolo,
            wbhi + LB + WOFF_EPW, wblo + LB + WOFF_EPW,
            enc_pb + (size_t)l * DMOD, yp, nullptr, nullptr, NTOK, DMOD, DMOD, 1);
        ln_k<<<NTOK, 128>>>(yp, xp, enc_g + (size_t)l * DMOD, enc_b + (size_t)l * DMOD,
                            xp, xhi, xlo);

        // ---- FFN ----
        gemm_mma_k<<<dim3(16, 32), 256, GM_SMEM>>>(xhi, xlo,
            wbhi + LB + WOFF_W1, wblo + LB + WOFF_W1,
            ffn_b1 + (size_t)l * DFF, nullptr, hhi, hlo, NTOK, DFF, DMOD, 2);
        gemm_mma_k<<<dim3(4, 32), 256, GM_SMEM>>>(hhi, hlo,
            wbhi + LB + WOFF_W2, wblo + LB + WOFF_W2,
            ffn_b2 + (size_t)l * DMOD, yp, nullptr, nullptr, NTOK, DMOD, DFF, 1);
        ln_k<<<NTOK, 128>>>(yp, xp, ffn_g + (size_t)l * DMOD, ffn_b + (size_t)l * DMOD,
                            xp, xhi, xlo);
    }

    size_t copy_elems = (size_t)out_size < (size_t)X_ELEMS ? (size_t)out_size : (size_t)X_ELEMS;
    cudaMemcpyAsync(d_out, xp, copy_elems * sizeof(float), cudaMemcpyDeviceToDevice);
}

// round 8
// speedup vs baseline: 2.1944x; 1.2949x over previous
#include <cuda_runtime.h>
#include <cuda_bf16.h>
#include <cstdint>

// Problem constants
#define NL   6
#define NH   8
#define DMOD 512
#define DKV  64
#define DFF  2048
#define NB   8
#define SEQ  512
#define NTOK 4096          // NB*SEQ
#define NHB  64            // NH*NB

#define X_ELEMS   (NTOK*DMOD)                 // 2,097,152
#define ATT_PER_L ((size_t)NHB*SEQ*SEQ)       // 16,777,216
#define SLF_OFF   ((size_t)X_ELEMS)
#define ENC_OFF   (SLF_OFF + (size_t)NL*ATT_PER_L)
#define FULL_OUT  (ENC_OFF + (size_t)NL*ATT_PER_L)   // 203,423,744

// per-layer bf16 weight bank layout (element offsets)
#define WOFF_SQ   0
#define WOFF_SK   262144
#define WOFF_SV   524288
#define WOFF_SPW  786432
#define WOFF_EQ   1048576
#define WOFF_EK   1310720
#define WOFF_EV   1572864
#define WOFF_EPW  1835008
#define WOFF_W1   2097152
#define WOFF_W2   3145728
#define WL_SIZE   4194304

// ---------------- scratch (no allocations allowed) ----------------
__device__ float g_x  [NTOK*DMOD];
__device__ float g_y  [NTOK*DMOD];
__device__ __nv_bfloat16 g_qkvh[3*NHB*SEQ*DKV];   // q|k|v hi, head-major [hb][t][e]
__device__ __nv_bfloat16 g_qkvl[3*NHB*SEQ*DKV];   // q|k|v lo
__device__ __nv_bfloat16 g_xhi [NTOK*DMOD];
__device__ __nv_bfloat16 g_xlo [NTOK*DMOD];
__device__ __nv_bfloat16 g_ehi [NTOK*DMOD];
__device__ __nv_bfloat16 g_elo [NTOK*DMOD];
__device__ __nv_bfloat16 g_aohi[NTOK*DMOD];
__device__ __nv_bfloat16 g_aolo[NTOK*DMOD];
__device__ __nv_bfloat16 g_hhi [NTOK*DFF];
__device__ __nv_bfloat16 g_hlo [NTOK*DFF];
__device__ __nv_bfloat16 g_wbhi[(size_t)NL*WL_SIZE];
__device__ __nv_bfloat16 g_wblo[(size_t)NL*WL_SIZE];

// ---------------- helpers (baseline PTX only: sm_80-class) ----------------
__device__ __forceinline__ uint32_t smem_u32(const void* p) {
    uint32_t a;
    asm("{ .reg .u64 t; cvta.to.shared.u64 t, %1; cvt.u32.u64 %0, t; }" : "=r"(a) : "l"(p));
    return a;
}
__device__ __forceinline__ void cp16(uint32_t saddr, const void* g) {
    asm volatile("cp.async.cg.shared.global [%0], [%1], 16;" :: "r"(saddr), "l"(g));
}
#define CP_COMMIT() asm volatile("cp.async.commit_group;" ::: "memory")
#define CP_WAIT1()  asm volatile("cp.async.wait_group 1;" ::: "memory")
#define CP_WAIT0()  asm volatile("cp.async.wait_group 0;" ::: "memory")

__device__ __forceinline__ void ldsm_x4(uint32_t* r, uint32_t addr) {
    asm volatile("ldmatrix.sync.aligned.m8n8.x4.shared.b16 {%0,%1,%2,%3}, [%4];"
                 : "=r"(r[0]), "=r"(r[1]), "=r"(r[2]), "=r"(r[3]) : "r"(addr));
}
__device__ __forceinline__ void ldsm_x4_t(uint32_t* r, uint32_t addr) {
    asm volatile("ldmatrix.sync.aligned.m8n8.x4.trans.shared.b16 {%0,%1,%2,%3}, [%4];"
                 : "=r"(r[0]), "=r"(r[1]), "=r"(r[2]), "=r"(r[3]) : "r"(addr));
}
__device__ __forceinline__ void mma16816(float* d, const uint32_t* a, const uint32_t* b) {
    asm volatile("mma.sync.aligned.m16n8k16.row.col.f32.bf16.bf16.f32 "
                 "{%0,%1,%2,%3}, {%4,%5,%6,%7}, {%8,%9}, {%0,%1,%2,%3};"
                 : "+f"(d[0]), "+f"(d[1]), "+f"(d[2]), "+f"(d[3])
                 : "r"(a[0]), "r"(a[1]), "r"(a[2]), "r"(a[3]), "r"(b[0]), "r"(b[1]));
}

__device__ __forceinline__ void fsplit(float v, __nv_bfloat16& h, __nv_bfloat16& l) {
    h = __float2bfloat16(v);
    l = __float2bfloat16(v - __bfloat162float(h));
}

// ---------------- embedding (fp32 x + bf16 hi/lo) ----------------
__global__ void embed_k(const int* __restrict__ seq, const int* __restrict__ pos,
                        const float* __restrict__ wemb, const float* __restrict__ pemb,
                        float* __restrict__ x,
                        __nv_bfloat16* __restrict__ xhi, __nv_bfloat16* __restrict__ xlo) {
    int n = blockIdx.x;
    int s = seq[n], p = pos[n];
    const float* we = wemb + (size_t)s * DMOD;
    const float* pe = pemb + (size_t)p * DMOD;
    for (int c = threadIdx.x; c < DMOD; c += blockDim.x) {
        float v = we[c] + pe[c];
        x[(size_t)n * DMOD + c] = v;
        __nv_bfloat16 h, l; fsplit(v, h, l);
        xhi[(size_t)n * DMOD + c] = h;
        xlo[(size_t)n * DMOD + c] = l;
    }
}

// ---------------- fp32 -> bf16 hi/lo split (for enc_output) ----------------
__global__ void conv_split_k(const float* __restrict__ src,
                             __nv_bfloat16* __restrict__ hi, __nv_bfloat16* __restrict__ lo,
                             int n) {
    int i = blockIdx.x * blockDim.x + threadIdx.x;
    if (i < n) {
        __nv_bfloat16 h, l; fsplit(src[i], h, l);
        hi[i] = h; lo[i] = l;
    }
}

// ---------------- qkv weight repack: [H,D,DK] fp32 -> B[n=h*64+e][k=d] bf16 hi/lo ----------------
__global__ void qkv_repack_tc(const float* __restrict__ src,
                              __nv_bfloat16* __restrict__ dhi, __nv_bfloat16* __restrict__ dlo) {
    __shared__ float t[64][65];
    int h = blockIdx.x >> 3, dt = blockIdx.x & 7;
    int d0 = dt * 64;
    int tid = threadIdx.x;
    for (int i = tid; i < 4096; i += 256) {
        int d = i >> 6, e = i & 63;
        t[e][d] = src[h * (DMOD * DKV) + (d0 + d) * DKV + e];
    }
    __syncthreads();
    for (int i = tid; i < 4096; i += 256) {
        int e = i >> 6, d = i & 63;
        __nv_bfloat16 hh, ll; fsplit(t[e][d], hh, ll);
        size_t o = (size_t)(h * 64 + e) * DMOD + d0 + d;
        dhi[o] = hh; dlo[o] = ll;
    }
}

// ---------------- generic transpose+split: src fp32 [R,C] -> dst bf16 [C,R] ----------------
__global__ void trans_conv_k(const float* __restrict__ src,
                             __nv_bfloat16* __restrict__ dhi, __nv_bfloat16* __restrict__ dlo,
                             int R, int C) {
    __shared__ float t[32][33];
    int c0 = blockIdx.x * 32, r0 = blockIdx.y * 32;
    int x = threadIdx.x, y = threadIdx.y;        // 32 x 8
    for (int yy = y; yy < 32; yy += 8)
        t[yy][x] = src[(size_t)(r0 + yy) * C + c0 + x];
    __syncthreads();
    for (int yy = y; yy < 32; yy += 8) {
        __nv_bfloat16 hh, ll; fsplit(t[x][yy], hh, ll);
        size_t o = (size_t)(c0 + yy) * R + r0 + x;
        dhi[o] = hh; dlo[o] = ll;
    }
}

// ---------------- mma.sync bf16-split GEMM: C[M,N] = A[M,K] @ B[N,K]^T ----------------
// 3 passes: Ahi*Bhi + Ahi*Blo + Alo*Bhi, fp32 register accumulators.
// mode 1: +bias -> fp32 Cf;  mode 2: +bias,relu -> bf16 Chi/Clo;
// mode 3: qkv scatter -> bf16 hi/lo Chi/Clo head-major.
#define GM_PITCH 40                  // bf16 elems per smem row (80B, conflict-free ldmatrix)
#define GM_TILEB (128*GM_PITCH*2)    // 10240 B per 128x32 tile
#define GM_STAGE (4*GM_TILEB)        // Ahi|Alo|Bhi|Blo = 40960 B
#define GM_SMEM  (2*GM_STAGE)        // 81920 B double buffered

__global__ __launch_bounds__(256, 1) void gemm_mma_k(
    const __nv_bfloat16* __restrict__ Ahi, const __nv_bfloat16* __restrict__ Alo,
    const __nv_bfloat16* __restrict__ Bhi, const __nv_bfloat16* __restrict__ Blo,
    const float* __restrict__ bias,
    float* __restrict__ Cf,
    __nv_bfloat16* __restrict__ Chi, __nv_bfloat16* __restrict__ Clo,
    int M, int N, int K, int mode)
{
    extern __shared__ __align__(16) char smem[];
    uint32_t sb = smem_u32(smem);
    const int tid = threadIdx.x, lane = tid & 31, w = tid >> 5;
    const int wm = w >> 2, wn = w & 3;          // warp grid 2 x 4 -> 64 x 32 tiles
    const int n0 = blockIdx.x * 128, m0 = blockIdx.y * 128;

    const __nv_bfloat16* srcs[4] = {
        Ahi + (size_t)m0 * K, Alo + (size_t)m0 * K,
        Bhi + (size_t)n0 * K, Blo + (size_t)n0 * K };

    const int seg0 = tid * 2;
    const int lrow = seg0 >> 2, lc = seg0 & 3;

    auto load_chunk = [&](int kc, int st) {
        const int k0 = kc * 32;
        uint32_t stb = sb + st * GM_STAGE;
#pragma unroll
        for (int t = 0; t < 4; t++) {
            const __nv_bfloat16* src = srcs[t] + k0 + (size_t)lrow * K + lc * 8;
            uint32_t tb = stb + t * GM_TILEB + (lrow * GM_PITCH + lc * 8) * 2;
            cp16(tb, src);
            cp16(tb + 16, src + 8);
        }
    };

    float acc[4][4][4];
#pragma unroll
    for (int a = 0; a < 4; a++)
#pragma unroll
        for (int b = 0; b < 4; b++)
#pragma unroll
            for (int c = 0; c < 4; c++) acc[a][b][c] = 0.f;

    const int nch = K >> 5;
    load_chunk(0, 0); CP_COMMIT();

    const uint32_t a_off = ((wm * 64 + (lane & 15)) * GM_PITCH + ((lane >> 4) << 3)) * 2;
    const uint32_t b_off = (((wn * 32) + ((lane & 16) ? 8 : 0) + (lane & 7)) * GM_PITCH
                            + ((lane & 8) ? 8 : 0)) * 2;

    for (int kc = 0; kc < nch; kc++) {
        if (kc + 1 < nch) { load_chunk(kc + 1, (kc + 1) & 1); CP_COMMIT(); CP_WAIT1(); }
        else { CP_WAIT0(); }
        __syncthreads();

        uint32_t stb = sb + (kc & 1) * GM_STAGE;
#pragma unroll
        for (int ks = 0; ks < 2; ks++) {
            uint32_t ah[4][4], al[4][4], bh[2][4], bl[2][4];
            const uint32_t kso = ks * 32;
#pragma unroll
            for (int mi = 0; mi < 4; mi++) {
                uint32_t off = a_off + mi * 16 * GM_PITCH * 2 + kso;
                ldsm_x4(ah[mi], stb + 0 * GM_TILEB + off);
                ldsm_x4(al[mi], stb + 1 * GM_TILEB + off);
            }
#pragma unroll
            for (int bi = 0; bi < 2; bi++) {
                uint32_t off = b_off + bi * 16 * GM_PITCH * 2 + kso;
                ldsm_x4(bh[bi], stb + 2 * GM_TILEB + off);
                ldsm_x4(bl[bi], stb + 3 * GM_TILEB + off);
            }
#pragma unroll
            for (int mi = 0; mi < 4; mi++)
#pragma unroll
                for (int ni = 0; ni < 4; ni++) {
                    const uint32_t* bhf = &bh[ni >> 1][(ni & 1) * 2];
                    const uint32_t* blf = &bl[ni >> 1][(ni & 1) * 2];
                    mma16816(acc[mi][ni], ah[mi], bhf);
                    mma16816(acc[mi][ni], ah[mi], blf);
                    mma16816(acc[mi][ni], al[mi], bhf);
                }
        }
        __syncthreads();
    }

    // epilogue
#pragma unroll
    for (int mi = 0; mi < 4; mi++) {
        int r0 = m0 + wm * 64 + mi * 16 + (lane >> 2);
#pragma unroll
        for (int ni = 0; ni < 4; ni++) {
            int col = n0 + wn * 32 + ni * 8 + (lane & 3) * 2;
            float c0 = acc[mi][ni][0], c1 = acc[mi][ni][1];
            float c2 = acc[mi][ni][2], c3 = acc[mi][ni][3];
            if (mode == 3) {
                int m = col >> 9, hh_ = (col >> 6) & 7, e = col & 63;
#pragma unroll
                for (int rr = 0; rr < 2; rr++) {
                    int row = r0 + rr * 8;
                    int b_ = row >> 9, t = row & 511;
                    size_t off = (size_t)m * 2097152 +
                                 (((size_t)(hh_ * NB + b_) * SEQ + t) * DKV + e);
                    float v0 = rr ? c2 : c0, v1 = rr ? c3 : c1;
                    __nv_bfloat16 h0, l0, h1, l1;
                    fsplit(v0, h0, l0); fsplit(v1, h1, l1);
                    __nv_bfloat162 ph; ph.x = h0; ph.y = h1;
                    __nv_bfloat162 pl; pl.x = l0; pl.y = l1;
                    *(__nv_bfloat162*)(Chi + off) = ph;
                    *(__nv_bfloat162*)(Clo + off) = pl;
                }
            } else if (mode == 1) {
                float2 bv = *(const float2*)(bias + col);
                float2 v0; v0.x = c0 + bv.x; v0.y = c1 + bv.y;
                float2 v1; v1.x = c2 + bv.x; v1.y = c3 + bv.y;
                *(float2*)(Cf + (size_t)r0 * N + col)       = v0;
                *(float2*)(Cf + (size_t)(r0 + 8) * N + col) = v1;
            } else {
                float2 bv = *(const float2*)(bias + col);
                float p0 = fmaxf(c0 + bv.x, 0.f), p1 = fmaxf(c1 + bv.y, 0.f);
                float p2 = fmaxf(c2 + bv.x, 0.f), p3 = fmaxf(c3 + bv.y, 0.f);
                __nv_bfloat16 h0, l0, h1, l1, h2, l2, h3, l3;
                fsplit(p0, h0, l0); fsplit(p1, h1, l1);
                fsplit(p2, h2, l2); fsplit(p3, h3, l3);
                __nv_bfloat162 ph0; ph0.x = h0; ph0.y = h1;
                __nv_bfloat162 ph1; ph1.x = h2; ph1.y = h3;
                __nv_bfloat162 pl0; pl0.x = l0; pl0.y = l1;
                __nv_bfloat162 pl1; pl1.x = l2; pl1.y = l3;
                *(__nv_bfloat162*)(Chi + (size_t)r0 * N + col)       = ph0;
                *(__nv_bfloat162*)(Chi + (size_t)(r0 + 8) * N + col) = ph1;
                *(__nv_bfloat162*)(Clo + (size_t)r0 * N + col)       = pl0;
                *(__nv_bfloat162*)(Clo + (size_t)(r0 + 8) * N + col) = pl1;
            }
        }
    }
}

// ---------------- MMA attention ----------------
// Block = (qt, hb): 64 queries x 512 keys. 8 warps: wm = w&3 (16 rows), wn = w>>2 (half).
#define PT 72                      // bf16 pitch (144 B, 16B-phase conflict-free)
#define SC_PITCH 520
#define SC_OFF   0                 // fp32 [64][520] = 133120 B
#define QH_OFF   133120            // bf16 [64][72] = 9216 B
#define QL_OFF   (QH_OFF + 9216)
#define KV_OFF   (QL_OFF + 9216)   // 2 stages x (hi 9216 + lo 9216)
#define KV_STAGE 18432
#define PTH_OFF  (KV_OFF + 2*KV_STAGE)
#define PTL_OFF  (PTH_OFF + 9216)
#define BIAS_OFF (PTL_OFF + 9216)  // fp32 [512]
#define ATTN2_SMEM (BIAS_OFF + 2048)   // 208896 B

__global__ __launch_bounds__(256, 1) void attn_mma_k(
    const __nv_bfloat16* __restrict__ Qh, const __nv_bfloat16* __restrict__ Ql,
    const __nv_bfloat16* __restrict__ Kh, const __nv_bfloat16* __restrict__ Kl,
    const __nv_bfloat16* __restrict__ Vh, const __nv_bfloat16* __restrict__ Vl,
    const int* __restrict__ seq, float* __restrict__ probs,
    __nv_bfloat16* __restrict__ Ohi, __nv_bfloat16* __restrict__ Olo,
    int causal, int writeProbs)
{
    extern __shared__ __align__(16) char sm2[];
    uint32_t sbase = smem_u32(sm2);
    float* Sc = (float*)(sm2 + SC_OFF);
    float* biasS = (float*)(sm2 + BIAS_OFF);
    const int hb = blockIdx.y, qt = blockIdx.x;
    const int h = hb >> 3, b = hb & 7;
    const int tid = threadIdx.x, lane = tid & 31, w = tid >> 5;
    const int wm = w & 3, wn = w >> 2;
    const float scale = 0.044194173824159216f;   // 1/sqrt(512)

    for (int i = tid; i < 512; i += 256)
        biasS[i] = (seq[b * SEQ + i] == 0) ? -1e30f : 0.f;

    // Q tile -> smem (hi/lo)
    {
        int row = tid >> 2, s0 = (tid & 3) * 16;
        size_t gq = ((size_t)hb * SEQ + qt * 64 + row) * DKV + s0;
        *(uint4*)(sm2 + QH_OFF + (row * PT + s0) * 2)     = *(const uint4*)(Qh + gq);
        *(uint4*)(sm2 + QH_OFF + (row * PT + s0 + 8) * 2) = *(const uint4*)(Qh + gq + 8);
        *(uint4*)(sm2 + QL_OFF + (row * PT + s0) * 2)     = *(const uint4*)(Ql + gq);
        *(uint4*)(sm2 + QL_OFF + (row * PT + s0 + 8) * 2) = *(const uint4*)(Ql + gq + 8);
    }

    auto load_kv = [&](const __nv_bfloat16* Hs, const __nv_bfloat16* Ls, int st, int stage) {
        uint32_t sbst = sbase + KV_OFF + stage * KV_STAGE;
        size_t gbase = ((size_t)hb * SEQ + st * 64) * DKV;
#pragma unroll
        for (int j = 0; j < 2; j++) {
            int seg = tid + j * 256;
            int row = seg >> 3, c = (seg & 7) * 8;
            uint32_t so = sbst + (row * PT + c) * 2;
            cp16(so,        Hs + gbase + row * DKV + c);
            cp16(so + 9216, Ls + gbase + row * DKV + c);
        }
    };

    load_kv(Kh, Kl, 0, 0); CP_COMMIT();
    __syncthreads();

    // resident Q fragments
    uint32_t qhf[4][4], qlf[4][4];
#pragma unroll
    for (int ks = 0; ks < 4; ks++) {
        uint32_t addr = sbase + QH_OFF +
            ((wm * 16 + (lane & 15)) * PT + ks * 16 + ((lane >> 4) << 3)) * 2;
        ldsm_x4(qhf[ks], addr);
        ldsm_x4(qlf[ks], addr + 9216);
    }

    // ---- score phase ----
    for (int st = 0; st < 8; st++) {
        __syncthreads();
        if (st < 7) { load_kv(Kh, Kl, st + 1, (st + 1) & 1); CP_COMMIT(); CP_WAIT1(); }
        else { CP_WAIT0(); }
        __syncthreads();

        uint32_t kb = sbase + KV_OFF + (st & 1) * KV_STAGE;
        float acc[4][4];
#pragma unroll
        for (int i = 0; i < 4; i++)
#pragma unroll
            for (int j = 0; j < 4; j++) acc[i][j] = 0.f;

#pragma unroll
        for (int ks = 0; ks < 4; ks++) {
            uint32_t bh[2][4], bl[2][4];
#pragma unroll
            for (int np = 0; np < 2; np++) {
                uint32_t addr = kb + ((wn * 32 + np * 16 + (lane & 7) + ((lane & 16) ? 8 : 0)) * PT
                                      + ks * 16 + ((lane & 8) ? 8 : 0)) * 2;
                ldsm_x4(bh[np], addr);
                ldsm_x4(bl[np], addr + 9216);
            }
#pragma unroll
            for (int nt = 0; nt < 4; nt++) {
                const uint32_t* bhf = &bh[nt >> 1][(nt & 1) * 2];
                const uint32_t* blf = &bl[nt >> 1][(nt & 1) * 2];
                mma16816(acc[nt], qhf[ks], bhf);
                mma16816(acc[nt], qhf[ks], blf);
                mma16816(acc[nt], qlf[ks], bhf);
            }
        }

        int r0 = wm * 16 + (lane >> 2);
#pragma unroll
        for (int nt = 0; nt < 4; nt++) {
            int col = st * 64 + wn * 32 + nt * 8 + (lane & 3) * 2;
            float b0 = biasS[col], b1 = biasS[col + 1];
#pragma unroll
            for (int rr = 0; rr < 2; rr++) {
                int row = r0 + rr * 8;
                int tg = qt * 64 + row;
                float v0 = acc[nt][rr * 2 + 0] * scale + b0;
                float v1 = acc[nt][rr * 2 + 1] * scale + b1;
                if (causal) {
                    if (col > tg)     v0 = -1e30f;
                    if (col + 1 > tg) v1 = -1e30f;
                }
                float2 vv; vv.x = v0; vv.y = v1;
                *(float2*)(Sc + row * SC_PITCH + col) = vv;
            }
        }
    }
    __syncthreads();

    // ---- softmax (warp per 8 rows) + probs write ----
    {
        for (int r = 0; r < 8; r++) {
            int q = w * 8 + r;
            float* row = Sc + q * SC_PITCH;
            float mx = -3.0e38f;
            for (int c = lane; c < 512; c += 32) mx = fmaxf(mx, row[c]);
#pragma unroll
            for (int o = 16; o; o >>= 1) mx = fmaxf(mx, __shfl_xor_sync(0xffffffffu, mx, o));
            float sum = 0.f;
            for (int c = lane; c < 512; c += 32) {
                float e = __expf(row[c] - mx);
                row[c] = e;
                sum += e;
            }
#pragma unroll
            for (int o = 16; o; o >>= 1) sum += __shfl_xor_sync(0xffffffffu, sum, o);
            float inv = 1.f / sum;
            float* prow = probs + ((size_t)hb * SEQ + qt * 64 + q) * SEQ;
            for (int c = lane; c < 512; c += 32) {
                float p = row[c] * inv;
                row[c] = p;
                if (writeProbs) prow[c] = p;
            }
        }
    }

    // ---- P @ V phase ----
    load_kv(Vh, Vl, 0, 0); CP_COMMIT();
    float oacc[4][4];
#pragma unroll
    for (int i = 0; i < 4; i++)
#pragma unroll
        for (int j = 0; j < 4; j++) oacc[i][j] = 0.f;

    for (int st = 0; st < 8; st++) {
        __syncthreads();
        if (st < 7) { load_kv(Vh, Vl, st + 1, (st + 1) & 1); CP_COMMIT(); CP_WAIT1(); }
        else { CP_WAIT0(); }

        // convert P tile st -> bf16 hi/lo
        {
            int row = tid >> 2, cb = (tid & 3) * 16;
            const float* srow = Sc + row * SC_PITCH + st * 64 + cb;
            __nv_bfloat16* ph = (__nv_bfloat16*)(sm2 + PTH_OFF) + row * PT + cb;
            __nv_bfloat16* pl = (__nv_bfloat16*)(sm2 + PTL_OFF) + row * PT + cb;
#pragma unroll
            for (int j2 = 0; j2 < 16; j2 += 4) {
                float4 p4 = *(const float4*)(srow + j2);
                __nv_bfloat16 h0, l0, h1, l1, h2, l2, h3, l3;
                fsplit(p4.x, h0, l0); fsplit(p4.y, h1, l1);
                fsplit(p4.z, h2, l2); fsplit(p4.w, h3, l3);
                __nv_bfloat162 ha; ha.x = h0; ha.y = h1;
                __nv_bfloat162 hb2; hb2.x = h2; hb2.y = h3;
                __nv_bfloat162 la; la.x = l0; la.y = l1;
                __nv_bfloat162 lb; lb.x = l2; lb.y = l3;
                *(__nv_bfloat162*)(ph + j2)     = ha;
                *(__nv_bfloat162*)(ph + j2 + 2) = hb2;
                *(__nv_bfloat162*)(pl + j2)     = la;
                *(__nv_bfloat162*)(pl + j2 + 2) = lb;
            }
        }
        __syncthreads();

        uint32_t vb = sbase + KV_OFF + (st & 1) * KV_STAGE;
#pragma unroll
        for (int ks = 0; ks < 4; ks++) {
            uint32_t afh[4], afl[4], vbh[2][4], vbl[2][4];
            uint32_t aaddr = sbase + PTH_OFF +
                ((wm * 16 + (lane & 15)) * PT + ks * 16 + ((lane >> 4) << 3)) * 2;
            ldsm_x4(afh, aaddr);
            ldsm_x4(afl, aaddr + 9216);
#pragma unroll
            for (int np = 0; np < 2; np++) {
                uint32_t addr = vb + ((ks * 16 + (lane & 7) + ((lane & 8) ? 8 : 0)) * PT
                                      + wn * 32 + np * 16 + ((lane & 16) ? 8 : 0)) * 2;
                ldsm_x4_t(vbh[np], addr);
                ldsm_x4_t(vbl[np], addr + 9216);
            }
#pragma unroll
            for (int nt = 0; nt < 4; nt++) {
                const uint32_t* bhf = &vbh[nt >> 1][(nt & 1) * 2];
                const uint32_t* blf = &vbl[nt >> 1][(nt & 1) * 2];
                mma16816(oacc[nt], afh, bhf);
                mma16816(oacc[nt], afh, blf);
                mma16816(oacc[nt], afl, bhf);
            }
        }
    }

    // O epilogue -> bf16 hi/lo, layout [b*SEQ+t][h*64+e]
    int r0 = wm * 16 + (lane >> 2);
#pragma unroll
    for (int nt = 0; nt < 4; nt++) {
        int gc = h * DKV + wn * 32 + nt * 8 + (lane & 3) * 2;
#pragma unroll
        for (int rr = 0; rr < 2; rr++) {
            int row = b * SEQ + qt * 64 + r0 + rr * 8;
            float v0 = oacc[nt][rr * 2 + 0], v1 = oacc[nt][rr * 2 + 1];
            __nv_bfloat16 h0, l0, h1, l1;
            fsplit(v0, h0, l0); fsplit(v1, h1, l1);
            __nv_bfloat162 ph; ph.x = h0; ph.y = h1;
            __nv_bfloat162 pl; pl.x = l0; pl.y = l1;
            *(__nv_bfloat162*)(Ohi + (size_t)row * DMOD + gc) = ph;
            *(__nv_bfloat162*)(Olo + (size_t)row * DMOD + gc) = pl;
        }
    }
}

// ---------------- layernorm(y + res) -> fp32 out + bf16 hi/lo ----------------
__global__ __launch_bounds__(128) void ln_k(
    const float* __restrict__ y, const float* __restrict__ res,
    const float* __restrict__ g, const float* __restrict__ b,
    float* __restrict__ out,
    __nv_bfloat16* __restrict__ ohi, __nv_bfloat16* __restrict__ olo)
{
    __shared__ float red[8];
    int n = blockIdx.x, tid = threadIdx.x;
    int c = tid * 4;
    float4 yv = *(const float4*)(y   + (size_t)n * DMOD + c);
    float4 rv = *(const float4*)(res + (size_t)n * DMOD + c);
    float v0 = yv.x + rv.x, v1 = yv.y + rv.y, v2 = yv.z + rv.z, v3 = yv.w + rv.w;

    float s = v0 + v1 + v2 + v3;
    int lane = tid & 31, warp = tid >> 5;
#pragma unroll
    for (int o = 16; o; o >>= 1) s += __shfl_xor_sync(0xffffffffu, s, o);
    if (lane == 0) red[warp] = s;
    __syncthreads();
    float mu = (red[0] + red[1] + red[2] + red[3]) * (1.f / DMOD);

    float d0 = v0 - mu, d1 = v1 - mu, d2 = v2 - mu, d3 = v3 - mu;
    float ss = d0 * d0 + d1 * d1 + d2 * d2 + d3 * d3;
#pragma unroll
    for (int o = 16; o; o >>= 1) ss += __shfl_xor_sync(0xffffffffu, ss, o);
    if (lane == 0) red[4 + warp] = ss;
    __syncthreads();
    float var = (red[4] + red[5] + red[6] + red[7]) * (1.f / DMOD);
    float is = rsqrtf(var + 1e-5f);

    float4 gv = *(const float4*)(g + c);
    float4 bv = *(const float4*)(b + c);
    float4 ov;
    ov.x = d0 * is * gv.x + bv.x;
    ov.y = d1 * is * gv.y + bv.y;
    ov.z = d2 * is * gv.z + bv.z;
    ov.w = d3 * is * gv.w + bv.w;
    *(float4*)(out + (size_t)n * DMOD + c) = ov;

    __nv_bfloat16 h0, l0, h1, l1, h2, l2, h3, l3;
    fsplit(ov.x, h0, l0); fsplit(ov.y, h1, l1);
    fsplit(ov.z, h2, l2); fsplit(ov.w, h3, l3);
    __nv_bfloat162 ph0; ph0.x = h0; ph0.y = h1;
    __nv_bfloat162 ph1; ph1.x = h2; ph1.y = h3;
    __nv_bfloat162 pl0; pl0.x = l0; pl0.y = l1;
    __nv_bfloat162 pl1; pl1.x = l2; pl1.y = l3;
    *(__nv_bfloat162*)(ohi + (size_t)n * DMOD + c)     = ph0;
    *(__nv_bfloat162*)(ohi + (size_t)n * DMOD + c + 2) = ph1;
    *(__nv_bfloat162*)(olo + (size_t)n * DMOD + c)     = pl0;
    *(__nv_bfloat162*)(olo + (size_t)n * DMOD + c + 2) = pl1;
}

// ---------------- host ----------------
extern "C" void kernel_launch(void* const* d_in, const int* in_sizes, int n_in,
                              void* d_out, int out_size)
{
    const int*   tgt_seq = (const int*)d_in[0];
    const int*   tgt_pos = (const int*)d_in[1];
    const int*   src_seq = (const int*)d_in[2];
    const float* enc_out = (const float*)d_in[3];
    const float* tgt_emb = (const float*)d_in[4];
    const float* pos_emb = (const float*)d_in[5];
    const float* slf_wq  = (const float*)d_in[6];
    const float* slf_wk  = (const float*)d_in[7];
    const float* slf_wv  = (const float*)d_in[8];
    const float* slf_pw  = (const float*)d_in[9];
    const float* slf_pb  = (const float*)d_in[10];
    const float* slf_g   = (const float*)d_in[11];
    const float* slf_b   = (const float*)d_in[12];
    const float* enc_wq  = (const float*)d_in[13];
    const float* enc_wk  = (const float*)d_in[14];
    const float* enc_wv  = (const float*)d_in[15];
    const float* enc_pw  = (const float*)d_in[16];
    const float* enc_pb  = (const float*)d_in[17];
    const float* enc_g   = (const float*)d_in[18];
    const float* enc_b   = (const float*)d_in[19];
    const float* ffn_w1  = (const float*)d_in[20];
    const float* ffn_b1  = (const float*)d_in[21];
    const float* ffn_w2  = (const float*)d_in[22];
    const float* ffn_b2  = (const float*)d_in[23];
    const float* ffn_g   = (const float*)d_in[24];
    const float* ffn_b   = (const float*)d_in[25];

    float *xp, *yp;
    __nv_bfloat16 *qkvh, *qkvl, *xhi, *xlo, *ehi, *elo, *aohi, *aolo, *hhi, *hlo, *wbhi, *wblo;
    cudaGetSymbolAddress((void**)&xp,   g_x);
    cudaGetSymbolAddress((void**)&yp,   g_y);
    cudaGetSymbolAddress((void**)&qkvh, g_qkvh);
    cudaGetSymbolAddress((void**)&qkvl, g_qkvl);
    cudaGetSymbolAddress((void**)&xhi,  g_xhi);
    cudaGetSymbolAddress((void**)&xlo,  g_xlo);
    cudaGetSymbolAddress((void**)&ehi,  g_ehi);
    cudaGetSymbolAddress((void**)&elo,  g_elo);
    cudaGetSymbolAddress((void**)&aohi, g_aohi);
    cudaGetSymbolAddress((void**)&aolo, g_aolo);
    cudaGetSymbolAddress((void**)&hhi,  g_hhi);
    cudaGetSymbolAddress((void**)&hlo,  g_hlo);
    cudaGetSymbolAddress((void**)&wbhi, g_wbhi);
    cudaGetSymbolAddress((void**)&wblo, g_wblo);

    cudaFuncSetAttribute(attn_mma_k, cudaFuncAttributeMaxDynamicSharedMemorySize, ATTN2_SMEM);
    cudaFuncSetAttribute(gemm_mma_k, cudaFuncAttributeMaxDynamicSharedMemorySize, GM_SMEM);

    const int full = (out_size >= (int)FULL_OUT) ? 1 : 0;
    float* out_f = (float*)d_out;
    float* probs_slf = out_f + SLF_OFF;
    float* probs_enc = out_f + ENC_OFF;

    __nv_bfloat16* qh = qkvh;
    __nv_bfloat16* kh = qkvh + 2097152;
    __nv_bfloat16* vh = qkvh + 4194304;
    __nv_bfloat16* ql = qkvl;
    __nv_bfloat16* kl = qkvl + 2097152;
    __nv_bfloat16* vl = qkvl + 4194304;

    embed_k<<<NTOK, 128>>>(tgt_seq, tgt_pos, tgt_emb, pos_emb, xp, xhi, xlo);
    conv_split_k<<<(NTOK * DMOD) / 256, 256>>>(enc_out, ehi, elo, NTOK * DMOD);

    for (int l = 0; l < NL; l++) {
        size_t LB = (size_t)l * WL_SIZE;
        size_t wsz = (size_t)NH * DMOD * DKV;
        qkv_repack_tc<<<64, 256>>>(slf_wq + l * wsz, wbhi + LB + WOFF_SQ, wblo + LB + WOFF_SQ);
        qkv_repack_tc<<<64, 256>>>(slf_wk + l * wsz, wbhi + LB + WOFF_SK, wblo + LB + WOFF_SK);
        qkv_repack_tc<<<64, 256>>>(slf_wv + l * wsz, wbhi + LB + WOFF_SV, wblo + LB + WOFF_SV);
        qkv_repack_tc<<<64, 256>>>(enc_wq + l * wsz, wbhi + LB + WOFF_EQ, wblo + LB + WOFF_EQ);
        qkv_repack_tc<<<64, 256>>>(enc_wk + l * wsz, wbhi + LB + WOFF_EK, wblo + LB + WOFF_EK);
        qkv_repack_tc<<<64, 256>>>(enc_wv + l * wsz, wbhi + LB + WOFF_EV, wblo + LB + WOFF_EV);
        trans_conv_k<<<dim3(16, 16), dim3(32, 8)>>>(slf_pw + (size_t)l * DMOD * DMOD,
            wbhi + LB + WOFF_SPW, wblo + LB + WOFF_SPW, DMOD, DMOD);
        trans_conv_k<<<dim3(16, 16), dim3(32, 8)>>>(enc_pw + (size_t)l * DMOD * DMOD,
            wbhi + LB + WOFF_EPW, wblo + LB + WOFF_EPW, DMOD, DMOD);
        trans_conv_k<<<dim3(64, 16), dim3(32, 8)>>>(ffn_w1 + (size_t)l * DMOD * DFF,
            wbhi + LB + WOFF_W1, wblo + LB + WOFF_W1, DMOD, DFF);
        trans_conv_k<<<dim3(16, 64), dim3(32, 8)>>>(ffn_w2 + (size_t)l * DFF * DMOD,
            wbhi + LB + WOFF_W2, wblo + LB + WOFF_W2, DFF, DMOD);
    }

    dim3 gAttn(8, NHB);

    for (int l = 0; l < NL; l++) {
        size_t LB = (size_t)l * WL_SIZE;

        // ---- self attention: fused QKV (N=1536) ----
        gemm_mma_k<<<dim3(12, 32), 256, GM_SMEM>>>(xhi, xlo,
            wbhi + LB + WOFF_SQ, wblo + LB + WOFF_SQ,
            nullptr, nullptr, qkvh, qkvl, NTOK, 1536, DMOD, 3);
        attn_mma_k<<<gAttn, 256, ATTN2_SMEM>>>(qh, ql, kh, kl, vh, vl, tgt_seq,
            probs_slf + (size_t)l * ATT_PER_L, aohi, aolo, 1, full);
        gemm_mma_k<<<dim3(4, 32), 256, GM_SMEM>>>(aohi, aolo,
            wbhi + LB + WOFF_SPW, wblo + LB + WOFF_SPW,
            slf_pb + (size_t)l * DMOD, yp, nullptr, nullptr, NTOK, DMOD, DMOD, 1);
        ln_k<<<NTOK, 128>>>(yp, xp, slf_g + (size_t)l * DMOD, slf_b + (size_t)l * DMOD,
                            xp, xhi, xlo);

        // ---- cross attention: Q from x (N=512), fused KV from enc (N=1024) ----
        gemm_mma_k<<<dim3(4, 32), 256, GM_SMEM>>>(xhi, xlo,
            wbhi + LB + WOFF_EQ, wblo + LB + WOFF_EQ,
            nullptr, nullptr, qkvh, qkvl, NTOK, DMOD, DMOD, 3);
        gemm_mma_k<<<dim3(8, 32), 256, GM_SMEM>>>(ehi, elo,
            wbhi + LB + WOFF_EK, wblo + LB + WOFF_EK,
            nullptr, nullptr, qkvh + 2097152, qkvl + 2097152, NTOK, 1024, DMOD, 3);
        attn_mma_k<<<gAttn, 256, ATTN2_SMEM>>>(qh, ql, kh, kl, vh, vl, src_seq,
            probs_enc + (size_t)l * ATT_PER_L, aohi, aolo, 0, full);
        gemm_mma_k<<<dim3(4, 32), 256, GM_SMEM>>>(aohi, aolo,
            wbhi + LB + WOFF_EPW, wblo + LB + WOFF_EPW,
            enc_pb + (size_t)l * DMOD, yp, nullptr, nullptr, NTOK, DMOD, DMOD, 1);
        ln_k<<<NTOK, 128>>>(yp, xp, enc_g + (size_t)l * DMOD, enc_b + (size_t)l * DMOD,
                            xp, xhi, xlo);

        // ---- FFN ----
        gemm_mma_k<<<dim3(16, 32), 256, GM_SMEM>>>(xhi, xlo,
            wbhi + LB + WOFF_W1, wblo + LB + WOFF_W1,
            ffn_b1 + (size_t)l * DFF, nullptr, hhi, hlo, NTOK, DFF, DMOD, 2);
        gemm_mma_k<<<dim3(4, 32), 256, GM_SMEM>>>(hhi, hlo,
            wbhi + LB + WOFF_W2, wblo + LB + WOFF_W2,
            ffn_b2 + (size_t)l * DMOD, yp, nullptr, nullptr, NTOK, DMOD, DFF, 1);
        ln_k<<<NTOK, 128>>>(yp, xp, ffn_g + (size_t)l * DMOD, ffn_b + (size_t)l * DMOD,
                            xp, xhi, xlo);
    }

    size_t copy_elems = (size_t)out_size < (size_t)X_ELEMS ? (size_t)out_size : (size_t)X_ELEMS;
    cudaMemcpyAsync(d_out, xp, copy_elems * sizeof(float), cudaMemcpyDeviceToDevice);
}

// round 10
// speedup vs baseline: 2.3924x; 1.0903x over previous
#include <cuda_runtime.h>
#include <cuda_bf16.h>
#include <cstdint>

// Problem constants
#define NL   6
#define NH   8
#define DMOD 512
#define DKV  64
#define DFF  2048
#define NB   8
#define SEQ  512
#define NTOK 4096          // NB*SEQ
#define NHB  64            // NH*NB

#define X_ELEMS   (NTOK*DMOD)                 // 2,097,152
#define ATT_PER_L ((size_t)NHB*SEQ*SEQ)       // 16,777,216
#define SLF_OFF   ((size_t)X_ELEMS)
#define ENC_OFF   (SLF_OFF + (size_t)NL*ATT_PER_L)
#define FULL_OUT  (ENC_OFF + (size_t)NL*ATT_PER_L)   // 203,423,744

// per-layer bf16 weight bank layout (element offsets)
#define WOFF_SQ   0
#define WOFF_SK   262144
#define WOFF_SV   524288
#define WOFF_SPW  786432
#define WOFF_EQ   1048576
#define WOFF_EK   1310720
#define WOFF_EV   1572864
#define WOFF_EPW  1835008
#define WOFF_W1   2097152
#define WOFF_W2   3145728
#define WL_SIZE   4194304

// ---------------- scratch (no allocations allowed) ----------------
__device__ float g_x  [NTOK*DMOD];
__device__ float g_y  [NTOK*DMOD];
__device__ __nv_bfloat16 g_qkvh[3*NHB*SEQ*DKV];   // q|k|v hi, head-major [hb][t][e]
__device__ __nv_bfloat16 g_qkvl[3*NHB*SEQ*DKV];   // q|k|v lo
__device__ __nv_bfloat16 g_xhi [NTOK*DMOD];
__device__ __nv_bfloat16 g_xlo [NTOK*DMOD];
__device__ __nv_bfloat16 g_ehi [NTOK*DMOD];
__device__ __nv_bfloat16 g_elo [NTOK*DMOD];
__device__ __nv_bfloat16 g_aohi[NTOK*DMOD];
__device__ __nv_bfloat16 g_aolo[NTOK*DMOD];
__device__ __nv_bfloat16 g_hhi [NTOK*DFF];
__device__ __nv_bfloat16 g_hlo [NTOK*DFF];
__device__ __nv_bfloat16 g_wbhi[(size_t)NL*WL_SIZE];
__device__ __nv_bfloat16 g_wblo[(size_t)NL*WL_SIZE];

struct P6 { const float* p[6]; };

// ---------------- helpers (baseline PTX only: sm_80-class) ----------------
__device__ __forceinline__ uint32_t smem_u32(const void* p) {
    uint32_t a;
    asm("{ .reg .u64 t; cvta.to.shared.u64 t, %1; cvt.u32.u64 %0, t; }" : "=r"(a) : "l"(p));
    return a;
}
__device__ __forceinline__ void cp16(uint32_t saddr, const void* g) {
    asm volatile("cp.async.cg.shared.global [%0], [%1], 16;" :: "r"(saddr), "l"(g));
}
#define CP_COMMIT() asm volatile("cp.async.commit_group;" ::: "memory")
#define CP_WAIT1()  asm volatile("cp.async.wait_group 1;" ::: "memory")
#define CP_WAIT0()  asm volatile("cp.async.wait_group 0;" ::: "memory")

__device__ __forceinline__ void ldsm_x4(uint32_t* r, uint32_t addr) {
    asm volatile("ldmatrix.sync.aligned.m8n8.x4.shared.b16 {%0,%1,%2,%3}, [%4];"
                 : "=r"(r[0]), "=r"(r[1]), "=r"(r[2]), "=r"(r[3]) : "r"(addr));
}
__device__ __forceinline__ void ldsm_x4_t(uint32_t* r, uint32_t addr) {
    asm volatile("ldmatrix.sync.aligned.m8n8.x4.trans.shared.b16 {%0,%1,%2,%3}, [%4];"
                 : "=r"(r[0]), "=r"(r[1]), "=r"(r[2]), "=r"(r[3]) : "r"(addr));
}
__device__ __forceinline__ void mma16816(float* d, const uint32_t* a, const uint32_t* b) {
    asm volatile("mma.sync.aligned.m16n8k16.row.col.f32.bf16.bf16.f32 "
                 "{%0,%1,%2,%3}, {%4,%5,%6,%7}, {%8,%9}, {%0,%1,%2,%3};"
                 : "+f"(d[0]), "+f"(d[1]), "+f"(d[2]), "+f"(d[3])
                 : "r"(a[0]), "r"(a[1]), "r"(a[2]), "r"(a[3]), "r"(b[0]), "r"(b[1]));
}

__device__ __forceinline__ void fsplit(float v, __nv_bfloat16& h, __nv_bfloat16& l) {
    h = __float2bfloat16(v);
    l = __float2bfloat16(v - __bfloat162float(h));
}

// ---------------- embedding (fp32 x + bf16 hi/lo) ----------------
__global__ void embed_k(const int* __restrict__ seq, const int* __restrict__ pos,
                        const float* __restrict__ wemb, const float* __restrict__ pemb,
                        float* __restrict__ x,
                        __nv_bfloat16* __restrict__ xhi, __nv_bfloat16* __restrict__ xlo) {
    int n = blockIdx.x;
    int s = seq[n], p = pos[n];
    const float* we = wemb + (size_t)s * DMOD;
    const float* pe = pemb + (size_t)p * DMOD;
    for (int c = threadIdx.x; c < DMOD; c += blockDim.x) {
        float v = we[c] + pe[c];
        x[(size_t)n * DMOD + c] = v;
        __nv_bfloat16 h, l; fsplit(v, h, l);
        xhi[(size_t)n * DMOD + c] = h;
        xlo[(size_t)n * DMOD + c] = l;
    }
}

// ---------------- fp32 -> bf16 hi/lo split (for enc_output) ----------------
__global__ void conv_split_k(const float* __restrict__ src,
                             __nv_bfloat16* __restrict__ hi, __nv_bfloat16* __restrict__ lo,
                             int n) {
    int i = blockIdx.x * blockDim.x + threadIdx.x;
    if (i < n) {
        __nv_bfloat16 h, l; fsplit(src[i], h, l);
        hi[i] = h; lo[i] = l;
    }
}

// ---------------- batched qkv weight repack (all 6 tensors x 6 layers) ----------------
// src[t][l]: [H,D,DK] fp32 -> dst B[n=h*64+e][k=d] bf16 hi/lo at layer bank offset.
__global__ void qkv_repack_all(P6 srcs,
                               __nv_bfloat16* __restrict__ dhi_b,
                               __nv_bfloat16* __restrict__ dlo_b) {
    __shared__ float t[64][65];
    const int woff[6] = {WOFF_SQ, WOFF_SK, WOFF_SV, WOFF_EQ, WOFF_EK, WOFF_EV};
    int ti = blockIdx.y, l = blockIdx.z;
    const float* src = srcs.p[ti] + (size_t)l * (NH * DMOD * DKV);
    __nv_bfloat16* dhi = dhi_b + (size_t)l * WL_SIZE + woff[ti];
    __nv_bfloat16* dlo = dlo_b + (size_t)l * WL_SIZE + woff[ti];

    int h = blockIdx.x >> 3, dt = blockIdx.x & 7;
    int d0 = dt * 64;
    int tid = threadIdx.x;
    for (int i = tid; i < 4096; i += 256) {
        int d = i >> 6, e = i & 63;
        t[e][d] = src[h * (DMOD * DKV) + (d0 + d) * DKV + e];
    }
    __syncthreads();
    for (int i = tid; i < 4096; i += 256) {
        int e = i >> 6, d = i & 63;
        __nv_bfloat16 hh, ll; fsplit(t[e][d], hh, ll);
        size_t o = (size_t)(h * 64 + e) * DMOD + d0 + d;
        dhi[o] = hh; dlo[o] = ll;
    }
}

// ---------------- batched projection-weight transpose (slf_pw + enc_pw, all layers) ----------------
// z: bit0 = tensor (0 slf, 1 enc), bits>=1 = layer. 512x512 transpose per (t,l).
__global__ void pw_repack_all(const float* __restrict__ slf_pw, const float* __restrict__ enc_pw,
                              __nv_bfloat16* __restrict__ dhi_b, __nv_bfloat16* __restrict__ dlo_b) {
    __shared__ float t[32][33];
    int z = blockIdx.z, l = z >> 1, te = z & 1;
    const float* src = (te ? enc_pw : slf_pw) + (size_t)l * DMOD * DMOD;
    size_t doff = (size_t)l * WL_SIZE + (te ? WOFF_EPW : WOFF_SPW);
    __nv_bfloat16* dhi = dhi_b + doff;
    __nv_bfloat16* dlo = dlo_b + doff;

    int c0 = blockIdx.x * 32, r0 = blockIdx.y * 32;
    int x = threadIdx.x, y = threadIdx.y;        // 32 x 8
    for (int yy = y; yy < 32; yy += 8)
        t[yy][x] = src[(size_t)(r0 + yy) * DMOD + c0 + x];
    __syncthreads();
    for (int yy = y; yy < 32; yy += 8) {
        __nv_bfloat16 hh, ll; fsplit(t[x][yy], hh, ll);
        size_t o = (size_t)(c0 + yy) * DMOD + r0 + x;
        dhi[o] = hh; dlo[o] = ll;
    }
}

// ---------------- batched FFN weight transpose: [R,C] -> [C,R], all layers via z ----------------
__global__ void ffn_repack_all(const float* __restrict__ w,
                               __nv_bfloat16* __restrict__ dhi_b, __nv_bfloat16* __restrict__ dlo_b,
                               int R, int C, int woff) {
    __shared__ float t[32][33];
    int l = blockIdx.z;
    const float* src = w + (size_t)l * R * C;
    size_t doff = (size_t)l * WL_SIZE + woff;
    __nv_bfloat16* dhi = dhi_b + doff;
    __nv_bfloat16* dlo = dlo_b + doff;

    int c0 = blockIdx.x * 32, r0 = blockIdx.y * 32;
    int x = threadIdx.x, y = threadIdx.y;        // 32 x 8
    for (int yy = y; yy < 32; yy += 8)
        t[yy][x] = src[(size_t)(r0 + yy) * C + c0 + x];
    __syncthreads();
    for (int yy = y; yy < 32; yy += 8) {
        __nv_bfloat16 hh, ll; fsplit(t[x][yy], hh, ll);
        size_t o = (size_t)(c0 + yy) * R + r0 + x;
        dhi[o] = hh; dlo[o] = ll;
    }
}

// ---------------- mma.sync bf16-split GEMM: C[M,N] = A[M,K] @ B[N,K]^T ----------------
// 3 passes: Ahi*Bhi + Ahi*Blo + Alo*Bhi, fp32 register accumulators.
// mode 1: +bias -> fp32 Cf;  mode 2: +bias,relu -> bf16 Chi/Clo;
// mode 3: qkv scatter -> bf16 hi/lo Chi/Clo head-major.
#define GM_PITCH 40                  // bf16 elems per smem row (80B, conflict-free ldmatrix)
#define GM_TILEB (128*GM_PITCH*2)    // 10240 B per 128x32 tile
#define GM_STAGE (4*GM_TILEB)        // Ahi|Alo|Bhi|Blo = 40960 B
#define GM_SMEM  (2*GM_STAGE)        // 81920 B double buffered

__global__ __launch_bounds__(256, 1) void gemm_mma_k(
    const __nv_bfloat16* __restrict__ Ahi, const __nv_bfloat16* __restrict__ Alo,
    const __nv_bfloat16* __restrict__ Bhi, const __nv_bfloat16* __restrict__ Blo,
    const float* __restrict__ bias,
    float* __restrict__ Cf,
    __nv_bfloat16* __restrict__ Chi, __nv_bfloat16* __restrict__ Clo,
    int M, int N, int K, int mode)
{
    extern __shared__ __align__(16) char smem[];
    uint32_t sb = smem_u32(smem);
    const int tid = threadIdx.x, lane = tid & 31, w = tid >> 5;
    const int wm = w >> 2, wn = w & 3;          // warp grid 2 x 4 -> 64 x 32 tiles
    const int n0 = blockIdx.x * 128, m0 = blockIdx.y * 128;

    const __nv_bfloat16* srcs[4] = {
        Ahi + (size_t)m0 * K, Alo + (size_t)m0 * K,
        Bhi + (size_t)n0 * K, Blo + (size_t)n0 * K };

    const int seg0 = tid * 2;
    const int lrow = seg0 >> 2, lc = seg0 & 3;

    auto load_chunk = [&](int kc, int st) {
        const int k0 = kc * 32;
        uint32_t stb = sb + st * GM_STAGE;
#pragma unroll
        for (int t = 0; t < 4; t++) {
            const __nv_bfloat16* src = srcs[t] + k0 + (size_t)lrow * K + lc * 8;
            uint32_t tb = stb + t * GM_TILEB + (lrow * GM_PITCH + lc * 8) * 2;
            cp16(tb, src);
            cp16(tb + 16, src + 8);
        }
    };

    float acc[4][4][4];
#pragma unroll
    for (int a = 0; a < 4; a++)
#pragma unroll
        for (int b = 0; b < 4; b++)
#pragma unroll
            for (int c = 0; c < 4; c++) acc[a][b][c] = 0.f;

    const int nch = K >> 5;
    load_chunk(0, 0); CP_COMMIT();

    const uint32_t a_off = ((wm * 64 + (lane & 15)) * GM_PITCH + ((lane >> 4) << 3)) * 2;
    const uint32_t b_off = (((wn * 32) + ((lane & 16) ? 8 : 0) + (lane & 7)) * GM_PITCH
                            + ((lane & 8) ? 8 : 0)) * 2;

    for (int kc = 0; kc < nch; kc++) {
        if (kc + 1 < nch) { load_chunk(kc + 1, (kc + 1) & 1); CP_COMMIT(); CP_WAIT1(); }
        else { CP_WAIT0(); }
        __syncthreads();

        uint32_t stb = sb + (kc & 1) * GM_STAGE;
#pragma unroll
        for (int ks = 0; ks < 2; ks++) {
            uint32_t ah[4][4], al[4][4], bh[2][4], bl[2][4];
            const uint32_t kso = ks * 32;
#pragma unroll
            for (int mi = 0; mi < 4; mi++) {
                uint32_t off = a_off + mi * 16 * GM_PITCH * 2 + kso;
                ldsm_x4(ah[mi], stb + 0 * GM_TILEB + off);
                ldsm_x4(al[mi], stb + 1 * GM_TILEB + off);
            }
#pragma unroll
            for (int bi = 0; bi < 2; bi++) {
                uint32_t off = b_off + bi * 16 * GM_PITCH * 2 + kso;
                ldsm_x4(bh[bi], stb + 2 * GM_TILEB + off);
                ldsm_x4(bl[bi], stb + 3 * GM_TILEB + off);
            }
#pragma unroll
            for (int mi = 0; mi < 4; mi++)
#pragma unroll
                for (int ni = 0; ni < 4; ni++) {
                    const uint32_t* bhf = &bh[ni >> 1][(ni & 1) * 2];
                    const uint32_t* blf = &bl[ni >> 1][(ni & 1) * 2];
                    mma16816(acc[mi][ni], ah[mi], bhf);
                    mma16816(acc[mi][ni], ah[mi], blf);
                    mma16816(acc[mi][ni], al[mi], bhf);
                }
        }
        __syncthreads();
    }

    // epilogue
#pragma unroll
    for (int mi = 0; mi < 4; mi++) {
        int r0 = m0 + wm * 64 + mi * 16 + (lane >> 2);
#pragma unroll
        for (int ni = 0; ni < 4; ni++) {
            int col = n0 + wn * 32 + ni * 8 + (lane & 3) * 2;
            float c0 = acc[mi][ni][0], c1 = acc[mi][ni][1];
            float c2 = acc[mi][ni][2], c3 = acc[mi][ni][3];
            if (mode == 3) {
                int m = col >> 9, hh_ = (col >> 6) & 7, e = col & 63;
#pragma unroll
                for (int rr = 0; rr < 2; rr++) {
                    int row = r0 + rr * 8;
                    int b_ = row >> 9, t = row & 511;
                    size_t off = (size_t)m * 2097152 +
                                 (((size_t)(hh_ * NB + b_) * SEQ + t) * DKV + e);
                    float v0 = rr ? c2 : c0, v1 = rr ? c3 : c1;
                    __nv_bfloat16 h0, l0, h1, l1;
                    fsplit(v0, h0, l0); fsplit(v1, h1, l1);
                    __nv_bfloat162 ph; ph.x = h0; ph.y = h1;
                    __nv_bfloat162 pl; pl.x = l0; pl.y = l1;
                    *(__nv_bfloat162*)(Chi + off) = ph;
                    *(__nv_bfloat162*)(Clo + off) = pl;
                }
            } else if (mode == 1) {
                float2 bv = *(const float2*)(bias + col);
                float2 v0; v0.x = c0 + bv.x; v0.y = c1 + bv.y;
                float2 v1; v1.x = c2 + bv.x; v1.y = c3 + bv.y;
                *(float2*)(Cf + (size_t)r0 * N + col)       = v0;
                *(float2*)(Cf + (size_t)(r0 + 8) * N + col) = v1;
            } else {
                float2 bv = *(const float2*)(bias + col);
                float p0 = fmaxf(c0 + bv.x, 0.f), p1 = fmaxf(c1 + bv.y, 0.f);
                float p2 = fmaxf(c2 + bv.x, 0.f), p3 = fmaxf(c3 + bv.y, 0.f);
                __nv_bfloat16 h0, l0, h1, l1, h2, l2, h3, l3;
                fsplit(p0, h0, l0); fsplit(p1, h1, l1);
                fsplit(p2, h2, l2); fsplit(p3, h3, l3);
                __nv_bfloat162 ph0; ph0.x = h0; ph0.y = h1;
                __nv_bfloat162 ph1; ph1.x = h2; ph1.y = h3;
                __nv_bfloat162 pl0; pl0.x = l0; pl0.y = l1;
                __nv_bfloat162 pl1; pl1.x = l2; pl1.y = l3;
                *(__nv_bfloat162*)(Chi + (size_t)r0 * N + col)       = ph0;
                *(__nv_bfloat162*)(Chi + (size_t)(r0 + 8) * N + col) = ph1;
                *(__nv_bfloat162*)(Clo + (size_t)r0 * N + col)       = pl0;
                *(__nv_bfloat162*)(Clo + (size_t)(r0 + 8) * N + col) = pl1;
            }
        }
    }
}

// ---------------- MMA attention ----------------
// Block = (qt, hb): 64 queries x 512 keys. 8 warps: wm = w&3 (16 rows), wn = w>>2 (half).
#define PT 72                      // bf16 pitch (144 B, 16B-phase conflict-free)
#define SC_PITCH 520
#define SC_OFF   0                 // fp32 [64][520] = 133120 B
#define QH_OFF   133120            // bf16 [64][72] = 9216 B
#define QL_OFF   (QH_OFF + 9216)
#define KV_OFF   (QL_OFF + 9216)   // 2 stages x (hi 9216 + lo 9216)
#define KV_STAGE 18432
#define PTH_OFF  (KV_OFF + 2*KV_STAGE)
#define PTL_OFF  (PTH_OFF + 9216)
#define BIAS_OFF (PTL_OFF + 9216)  // fp32 [512]
#define ATTN2_SMEM (BIAS_OFF + 2048)   // 208896 B

__global__ __launch_bounds__(256, 1) void attn_mma_k(
    const __nv_bfloat16* __restrict__ Qh, const __nv_bfloat16* __restrict__ Ql,
    const __nv_bfloat16* __restrict__ Kh, const __nv_bfloat16* __restrict__ Kl,
    const __nv_bfloat16* __restrict__ Vh, const __nv_bfloat16* __restrict__ Vl,
    const int* __restrict__ seq, float* __restrict__ probs,
    __nv_bfloat16* __restrict__ Ohi, __nv_bfloat16* __restrict__ Olo,
    int causal, int writeProbs)
{
    extern __shared__ __align__(16) char sm2[];
    uint32_t sbase = smem_u32(sm2);
    float* Sc = (float*)(sm2 + SC_OFF);
    float* biasS = (float*)(sm2 + BIAS_OFF);
    const int hb = blockIdx.y, qt = blockIdx.x;
    const int h = hb >> 3, b = hb & 7;
    const int tid = threadIdx.x, lane = tid & 31, w = tid >> 5;
    const int wm = w & 3, wn = w >> 2;
    const float scale = 0.044194173824159216f;   // 1/sqrt(512)

    for (int i = tid; i < 512; i += 256)
        biasS[i] = (seq[b * SEQ + i] == 0) ? -1e30f : 0.f;

    // Q tile -> smem (hi/lo)
    {
        int row = tid >> 2, s0 = (tid & 3) * 16;
        size_t gq = ((size_t)hb * SEQ + qt * 64 + row) * DKV + s0;
        *(uint4*)(sm2 + QH_OFF + (row * PT + s0) * 2)     = *(const uint4*)(Qh + gq);
        *(uint4*)(sm2 + QH_OFF + (row * PT + s0 + 8) * 2) = *(const uint4*)(Qh + gq + 8);
        *(uint4*)(sm2 + QL_OFF + (row * PT + s0) * 2)     = *(const uint4*)(Ql + gq);
        *(uint4*)(sm2 + QL_OFF + (row * PT + s0 + 8) * 2) = *(const uint4*)(Ql + gq + 8);
    }

    auto load_kv = [&](const __nv_bfloat16* Hs, const __nv_bfloat16* Ls, int st, int stage) {
        uint32_t sbst = sbase + KV_OFF + stage * KV_STAGE;
        size_t gbase = ((size_t)hb * SEQ + st * 64) * DKV;
#pragma unroll
        for (int j = 0; j < 2; j++) {
            int seg = tid + j * 256;
            int row = seg >> 3, c = (seg & 7) * 8;
            uint32_t so = sbst + (row * PT + c) * 2;
            cp16(so,        Hs + gbase + row * DKV + c);
            cp16(so + 9216, Ls + gbase + row * DKV + c);
        }
    };

    load_kv(Kh, Kl, 0, 0); CP_COMMIT();
    __syncthreads();

    // resident Q fragments
    uint32_t qhf[4][4], qlf[4][4];
#pragma unroll
    for (int ks = 0; ks < 4; ks++) {
        uint32_t addr = sbase + QH_OFF +
            ((wm * 16 + (lane & 15)) * PT + ks * 16 + ((lane >> 4) << 3)) * 2;
        ldsm_x4(qhf[ks], addr);
        ldsm_x4(qlf[ks], addr + 9216);
    }

    // ---- score phase ----
    for (int st = 0; st < 8; st++) {
        __syncthreads();
        if (st < 7) { load_kv(Kh, Kl, st + 1, (st + 1) & 1); CP_COMMIT(); CP_WAIT1(); }
        else { CP_WAIT0(); }
        __syncthreads();

        uint32_t kb = sbase + KV_OFF + (st & 1) * KV_STAGE;
        float acc[4][4];
#pragma unroll
        for (int i = 0; i < 4; i++)
#pragma unroll
            for (int j = 0; j < 4; j++) acc[i][j] = 0.f;

#pragma unroll
        for (int ks = 0; ks < 4; ks++) {
            uint32_t bh[2][4], bl[2][4];
#pragma unroll
            for (int np = 0; np < 2; np++) {
                uint32_t addr = kb + ((wn * 32 + np * 16 + (lane & 7) + ((lane & 16) ? 8 : 0)) * PT
                                      + ks * 16 + ((lane & 8) ? 8 : 0)) * 2;
                ldsm_x4(bh[np], addr);
                ldsm_x4(bl[np], addr + 9216);
            }
#pragma unroll
            for (int nt = 0; nt < 4; nt++) {
                const uint32_t* bhf = &bh[nt >> 1][(nt & 1) * 2];
                const uint32_t* blf = &bl[nt >> 1][(nt & 1) * 2];
                mma16816(acc[nt], qhf[ks], bhf);
                mma16816(acc[nt], qhf[ks], blf);
                mma16816(acc[nt], qlf[ks], bhf);
            }
        }

        int r0 = wm * 16 + (lane >> 2);
#pragma unroll
        for (int nt = 0; nt < 4; nt++) {
            int col = st * 64 + wn * 32 + nt * 8 + (lane & 3) * 2;
            float b0 = biasS[col], b1 = biasS[col + 1];
#pragma unroll
            for (int rr = 0; rr < 2; rr++) {
                int row = r0 + rr * 8;
                int tg = qt * 64 + row;
                float v0 = acc[nt][rr * 2 + 0] * scale + b0;
                float v1 = acc[nt][rr * 2 + 1] * scale + b1;
                if (causal) {
                    if (col > tg)     v0 = -1e30f;
                    if (col + 1 > tg) v1 = -1e30f;
                }
                float2 vv; vv.x = v0; vv.y = v1;
                *(float2*)(Sc + row * SC_PITCH + col) = vv;
            }
        }
    }
    __syncthreads();

    // ---- softmax (warp per 8 rows) + probs write ----
    {
        for (int r = 0; r < 8; r++) {
            int q = w * 8 + r;
            float* row = Sc + q * SC_PITCH;
            float mx = -3.0e38f;
            for (int c = lane; c < 512; c += 32) mx = fmaxf(mx, row[c]);
#pragma unroll
            for (int o = 16; o; o >>= 1) mx = fmaxf(mx, __shfl_xor_sync(0xffffffffu, mx, o));
            float sum = 0.f;
            for (int c = lane; c < 512; c += 32) {
                float e = __expf(row[c] - mx);
                row[c] = e;
                sum += e;
            }
#pragma unroll
            for (int o = 16; o; o >>= 1) sum += __shfl_xor_sync(0xffffffffu, sum, o);
            float inv = 1.f / sum;
            float* prow = probs + ((size_t)hb * SEQ + qt * 64 + q) * SEQ;
            for (int c = lane; c < 512; c += 32) {
                float p = row[c] * inv;
                row[c] = p;
                if (writeProbs) prow[c] = p;
            }
        }
    }

    // ---- P @ V phase ----
    load_kv(Vh, Vl, 0, 0); CP_COMMIT();
    float oacc[4][4];
#pragma unroll
    for (int i = 0; i < 4; i++)
#pragma unroll
        for (int j = 0; j < 4; j++) oacc[i][j] = 0.f;

    for (int st = 0; st < 8; st++) {
        __syncthreads();
        if (st < 7) { load_kv(Vh, Vl, st + 1, (st + 1) & 1); CP_COMMIT(); CP_WAIT1(); }
        else { CP_WAIT0(); }

        // convert P tile st -> bf16 hi/lo
        {
            int row = tid >> 2, cb = (tid & 3) * 16;
            const float* srow = Sc + row * SC_PITCH + st * 64 + cb;
            __nv_bfloat16* ph = (__nv_bfloat16*)(sm2 + PTH_OFF) + row * PT + cb;
            __nv_bfloat16* pl = (__nv_bfloat16*)(sm2 + PTL_OFF) + row * PT + cb;
#pragma unroll
            for (int j2 = 0; j2 < 16; j2 += 4) {
                float4 p4 = *(const float4*)(srow + j2);
                __nv_bfloat16 h0, l0, h1, l1, h2, l2, h3, l3;
                fsplit(p4.x, h0, l0); fsplit(p4.y, h1, l1);
                fsplit(p4.z, h2, l2); fsplit(p4.w, h3, l3);
                __nv_bfloat162 ha; ha.x = h0; ha.y = h1;
                __nv_bfloat162 hb2; hb2.x = h2; hb2.y = h3;
                __nv_bfloat162 la; la.x = l0; la.y = l1;
                __nv_bfloat162 lb; lb.x = l2; lb.y = l3;
                *(__nv_bfloat162*)(ph + j2)     = ha;
                *(__nv_bfloat162*)(ph + j2 + 2) = hb2;
                *(__nv_bfloat162*)(pl + j2)     = la;
                *(__nv_bfloat162*)(pl + j2 + 2) = lb;
            }
        }
        __syncthreads();

        uint32_t vb = sbase + KV_OFF + (st & 1) * KV_STAGE;
#pragma unroll
        for (int ks = 0; ks < 4; ks++) {
            uint32_t afh[4], afl[4], vbh[2][4], vbl[2][4];
            uint32_t aaddr = sbase + PTH_OFF +
                ((wm * 16 + (lane & 15)) * PT + ks * 16 + ((lane >> 4) << 3)) * 2;
            ldsm_x4(afh, aaddr);
            ldsm_x4(afl, aaddr + 9216);
#pragma unroll
            for (int np = 0; np < 2; np++) {
                uint32_t addr = vb + ((ks * 16 + (lane & 7) + ((lane & 8) ? 8 : 0)) * PT
                                      + wn * 32 + np * 16 + ((lane & 16) ? 8 : 0)) * 2;
                ldsm_x4_t(vbh[np], addr);
                ldsm_x4_t(vbl[np], addr + 9216);
            }
#pragma unroll
            for (int nt = 0; nt < 4; nt++) {
                const uint32_t* bhf = &vbh[nt >> 1][(nt & 1) * 2];
                const uint32_t* blf = &vbl[nt >> 1][(nt & 1) * 2];
                mma16816(oacc[nt], afh, bhf);
                mma16816(oacc[nt], afh, blf);
                mma16816(oacc[nt], afl, bhf);
            }
        }
    }

    // O epilogue -> bf16 hi/lo, layout [b*SEQ+t][h*64+e]
    int r0 = wm * 16 + (lane >> 2);
#pragma unroll
    for (int nt = 0; nt < 4; nt++) {
        int gc = h * DKV + wn * 32 + nt * 8 + (lane & 3) * 2;
#pragma unroll
        for (int rr = 0; rr < 2; rr++) {
            int row = b * SEQ + qt * 64 + r0 + rr * 8;
            float v0 = oacc[nt][rr * 2 + 0], v1 = oacc[nt][rr * 2 + 1];
            __nv_bfloat16 h0, l0, h1, l1;
            fsplit(v0, h0, l0); fsplit(v1, h1, l1);
            __nv_bfloat162 ph; ph.x = h0; ph.y = h1;
            __nv_bfloat162 pl; pl.x = l0; pl.y = l1;
            *(__nv_bfloat162*)(Ohi + (size_t)row * DMOD + gc) = ph;
            *(__nv_bfloat162*)(Olo + (size_t)row * DMOD + gc) = pl;
        }
    }
}

// ---------------- layernorm(y + res) -> fp32 out + bf16 hi/lo ----------------
__global__ __launch_bounds__(128) void ln_k(
    const float* __restrict__ y, const float* __restrict__ res,
    const float* __restrict__ g, const float* __restrict__ b,
    float* __restrict__ out,
    __nv_bfloat16* __restrict__ ohi, __nv_bfloat16* __restrict__ olo)
{
    __shared__ float red[8];
    int n = blockIdx.x, tid = threadIdx.x;
    int c = tid * 4;
    float4 yv = *(const float4*)(y   + (size_t)n * DMOD + c);
    float4 rv = *(const float4*)(res + (size_t)n * DMOD + c);
    float v0 = yv.x + rv.x, v1 = yv.y + rv.y, v2 = yv.z + rv.z, v3 = yv.w + rv.w;

    float s = v0 + v1 + v2 + v3;
    int lane = tid & 31, warp = tid >> 5;
#pragma unroll
    for (int o = 16; o; o >>= 1) s += __shfl_xor_sync(0xffffffffu, s, o);
    if (lane == 0) red[warp] = s;
    __syncthreads();
    float mu = (red[0] + red[1] + red[2] + red[3]) * (1.f / DMOD);

    float d0 = v0 - mu, d1 = v1 - mu, d2 = v2 - mu, d3 = v3 - mu;
    float ss = d0 * d0 + d1 * d1 + d2 * d2 + d3 * d3;
#pragma unroll
    for (int o = 16; o; o >>= 1) ss += __shfl_xor_sync(0xffffffffu, ss, o);
    if (lane == 0) red[4 + warp] = ss;
    __syncthreads();
    float var = (red[4] + red[5] + red[6] + red[7]) * (1.f / DMOD);
    float is = rsqrtf(var + 1e-5f);

    float4 gv = *(const float4*)(g + c);
    float4 bv = *(const float4*)(b + c);
    float4 ov;
    ov.x = d0 * is * gv.x + bv.x;
    ov.y = d1 * is * gv.y + bv.y;
    ov.z = d2 * is * gv.z + bv.z;
    ov.w = d3 * is * gv.w + bv.w;
    *(float4*)(out + (size_t)n * DMOD + c) = ov;

    __nv_bfloat16 h0, l0, h1, l1, h2, l2, h3, l3;
    fsplit(ov.x, h0, l0); fsplit(ov.y, h1, l1);
    fsplit(ov.z, h2, l2); fsplit(ov.w, h3, l3);
    __nv_bfloat162 ph0; ph0.x = h0; ph0.y = h1;
    __nv_bfloat162 ph1; ph1.x = h2; ph1.y = h3;
    __nv_bfloat162 pl0; pl0.x = l0; pl0.y = l1;
    __nv_bfloat162 pl1; pl1.x = l2; pl1.y = l3;
    *(__nv_bfloat162*)(ohi + (size_t)n * DMOD + c)     = ph0;
    *(__nv_bfloat162*)(ohi + (size_t)n * DMOD + c + 2) = ph1;
    *(__nv_bfloat162*)(olo + (size_t)n * DMOD + c)     = pl0;
    *(__nv_bfloat162*)(olo + (size_t)n * DMOD + c + 2) = pl1;
}

// ---------------- host ----------------
extern "C" void kernel_launch(void* const* d_in, const int* in_sizes, int n_in,
                              void* d_out, int out_size)
{
    const int*   tgt_seq = (const int*)d_in[0];
    const int*   tgt_pos = (const int*)d_in[1];
    const int*   src_seq = (const int*)d_in[2];
    const float* enc_out = (const float*)d_in[3];
    const float* tgt_emb = (const float*)d_in[4];
    const float* pos_emb = (const float*)d_in[5];
    const float* slf_wq  = (const float*)d_in[6];
    const float* slf_wk  = (const float*)d_in[7];
    const float* slf_wv  = (const float*)d_in[8];
    const float* slf_pw  = (const float*)d_in[9];
    const float* slf_pb  = (const float*)d_in[10];
    const float* slf_g   = (const float*)d_in[11];
    const float* slf_b   = (const float*)d_in[12];
    const float* enc_wq  = (const float*)d_in[13];
    const float* enc_wk  = (const float*)d_in[14];
    const float* enc_wv  = (const float*)d_in[15];
    const float* enc_pw  = (const float*)d_in[16];
    const float* enc_pb  = (const float*)d_in[17];
    const float* enc_g   = (const float*)d_in[18];
    const float* enc_b   = (const float*)d_in[19];
    const float* ffn_w1  = (const float*)d_in[20];
    const float* ffn_b1  = (const float*)d_in[21];
    const float* ffn_w2  = (const float*)d_in[22];
    const float* ffn_b2  = (const float*)d_in[23];
    const float* ffn_g   = (const float*)d_in[24];
    const float* ffn_b   = (const float*)d_in[25];

    float *xp, *yp;
    __nv_bfloat16 *qkvh, *qkvl, *xhi, *xlo, *ehi, *elo, *aohi, *aolo, *hhi, *hlo, *wbhi, *wblo;
    cudaGetSymbolAddress((void**)&xp,   g_x);
    cudaGetSymbolAddress((void**)&yp,   g_y);
    cudaGetSymbolAddress((void**)&qkvh, g_qkvh);
    cudaGetSymbolAddress((void**)&qkvl, g_qkvl);
    cudaGetSymbolAddress((void**)&xhi,  g_xhi);
    cudaGetSymbolAddress((void**)&xlo,  g_xlo);
    cudaGetSymbolAddress((void**)&ehi,  g_ehi);
    cudaGetSymbolAddress((void**)&elo,  g_elo);
    cudaGetSymbolAddress((void**)&aohi, g_aohi);
    cudaGetSymbolAddress((void**)&aolo, g_aolo);
    cudaGetSymbolAddress((void**)&hhi,  g_hhi);
    cudaGetSymbolAddress((void**)&hlo,  g_hlo);
    cudaGetSymbolAddress((void**)&wbhi, g_wbhi);
    cudaGetSymbolAddress((void**)&wblo, g_wblo);

    cudaFuncSetAttribute(attn_mma_k, cudaFuncAttributeMaxDynamicSharedMemorySize, ATTN2_SMEM);
    cudaFuncSetAttribute(gemm_mma_k, cudaFuncAttributeMaxDynamicSharedMemorySize, GM_SMEM);

    const int full = (out_size >= (int)FULL_OUT) ? 1 : 0;
    float* out_f = (float*)d_out;
    float* probs_slf = out_f + SLF_OFF;
    float* probs_enc = out_f + ENC_OFF;

    __nv_bfloat16* qh = qkvh;
    __nv_bfloat16* kh = qkvh + 2097152;
    __nv_bfloat16* vh = qkvh + 4194304;
    __nv_bfloat16* ql = qkvl;
    __nv_bfloat16* kl = qkvl + 2097152;
    __nv_bfloat16* vl = qkvl + 4194304;

    embed_k<<<NTOK, 128>>>(tgt_seq, tgt_pos, tgt_emb, pos_emb, xp, xhi, xlo);
    conv_split_k<<<(NTOK * DMOD) / 256, 256>>>(enc_out, ehi, elo, NTOK * DMOD);

    // ---- batched weight prep: 4 launches for all 60 repacks ----
    {
        P6 srcs;
        srcs.p[0] = slf_wq; srcs.p[1] = slf_wk; srcs.p[2] = slf_wv;
        srcs.p[3] = enc_wq; srcs.p[4] = enc_wk; srcs.p[5] = enc_wv;
        qkv_repack_all<<<dim3(64, 6, 6), 256>>>(srcs, wbhi, wblo);
        pw_repack_all<<<dim3(16, 16, 12), dim3(32, 8)>>>(slf_pw, enc_pw, wbhi, wblo);
        ffn_repack_all<<<dim3(64, 16, 6), dim3(32, 8)>>>(ffn_w1, wbhi, wblo, DMOD, DFF, WOFF_W1);
        ffn_repack_all<<<dim3(16, 64, 6), dim3(32, 8)>>>(ffn_w2, wbhi, wblo, DFF, DMOD, WOFF_W2);
    }

    dim3 gAttn(8, NHB);

    for (int l = 0; l < NL; l++) {
        size_t LB = (size_t)l * WL_SIZE;

        // ---- self attention: fused QKV (N=1536) ----
        gemm_mma_k<<<dim3(12, 32), 256, GM_SMEM>>>(xhi, xlo,
            wbhi + LB + WOFF_SQ, wblo + LB + WOFF_SQ,
            nullptr, nullptr, qkvh, qkvl, NTOK, 1536, DMOD, 3);
        attn_mma_k<<<gAttn, 256, ATTN2_SMEM>>>(qh, ql, kh, kl, vh, vl, tgt_seq,
            probs_slf + (size_t)l * ATT_PER_L, aohi, aolo, 1, full);
        gemm_mma_k<<<dim3(4, 32), 256, GM_SMEM>>>(aohi, aolo,
            wbhi + LB + WOFF_SPW, wblo + LB + WOFF_SPW,
            slf_pb + (size_t)l * DMOD, yp, nullptr, nullptr, NTOK, DMOD, DMOD, 1);
        ln_k<<<NTOK, 128>>>(yp, xp, slf_g + (size_t)l * DMOD, slf_b + (size_t)l * DMOD,
                            xp, xhi, xlo);

        // ---- cross attention: Q from x (N=512), fused KV from enc (N=1024) ----
        gemm_mma_k<<<dim3(4, 32), 256, GM_SMEM>>>(xhi, xlo,
            wbhi + LB + WOFF_EQ, wblo + LB + WOFF_EQ,
            nullptr, nullptr, qkvh, qkvl, NTOK, DMOD, DMOD, 3);
        gemm_mma_k<<<dim3(8, 32), 256, GM_SMEM>>>(ehi, elo,
            wbhi + LB + WOFF_EK, wblo + LB + WOFF_EK,
            nullptr, nullptr, qkvh + 2097152, qkvl + 2097152, NTOK, 1024, DMOD, 3);
        attn_mma_k<<<gAttn, 256, ATTN2_SMEM>>>(qh, ql, kh, kl, vh, vl, src_seq,
            probs_enc + (size_t)l * ATT_PER_L, aohi, aolo, 0, full);
        gemm_mma_k<<<dim3(4, 32), 256, GM_SMEM>>>(aohi, aolo,
            wbhi + LB + WOFF_EPW, wblo + LB + WOFF_EPW,
            enc_pb + (size_t)l * DMOD, yp, nullptr, nullptr, NTOK, DMOD, DMOD, 1);
        ln_k<<<NTOK, 128>>>(yp, xp, enc_g + (size_t)l * DMOD, enc_b + (size_t)l * DMOD,
                            xp, xhi, xlo);

        // ---- FFN ----
        gemm_mma_k<<<dim3(16, 32), 256, GM_SMEM>>>(xhi, xlo,
            wbhi + LB + WOFF_W1, wblo + LB + WOFF_W1,
            ffn_b1 + (size_t)l * DFF, nullptr, hhi, hlo, NTOK, DFF, DMOD, 2);
        gemm_mma_k<<<dim3(4, 32), 256, GM_SMEM>>>(hhi, hlo,
            wbhi + LB + WOFF_W2, wblo + LB + WOFF_W2,
            ffn_b2 + (size_t)l * DMOD, yp, nullptr, nullptr, NTOK, DMOD, DFF, 1);
        ln_k<<<NTOK, 128>>>(yp, xp, ffn_g + (size_t)l * DMOD, ffn_b + (size_t)l * DMOD,
                            xp, xhi, xlo);
    }

    size_t copy_elems = (size_t)out_size < (size_t)X_ELEMS ? (size_t)out_size : (size_t)X_ELEMS;
    cudaMemcpyAsync(d_out, xp, copy_elems * sizeof(float), cudaMemcpyDeviceToDevice);
}

// round 11
// speedup vs baseline: 2.7144x; 1.1346x over previous
#include <cuda_runtime.h>
#include <cuda_bf16.h>
#include <cstdint>

// Problem constants
#define NL   6
#define NH   8
#define DMOD 512
#define DKV  64
#define DFF  2048
#define NB   8
#define SEQ  512
#define NTOK 4096          // NB*SEQ
#define NHB  64            // NH*NB

#define X_ELEMS   (NTOK*DMOD)                 // 2,097,152
#define ATT_PER_L ((size_t)NHB*SEQ*SEQ)       // 16,777,216
#define SLF_OFF   ((size_t)X_ELEMS)
#define ENC_OFF   (SLF_OFF + (size_t)NL*ATT_PER_L)
#define FULL_OUT  (ENC_OFF + (size_t)NL*ATT_PER_L)   // 203,423,744

// per-layer bf16 weight bank layout (element offsets)
#define WOFF_SQ   0
#define WOFF_SK   262144
#define WOFF_SV   524288
#define WOFF_SPW  786432
#define WOFF_EQ   1048576
#define WOFF_EK   1310720
#define WOFF_EV   1572864
#define WOFF_EPW  1835008
#define WOFF_W1   2097152
#define WOFF_W2   3145728
#define WL_SIZE   4194304

// ---------------- scratch (no allocations allowed) ----------------
__device__ float g_x  [NTOK*DMOD];
__device__ float g_y  [NTOK*DMOD];
__device__ __nv_bfloat16 g_qkvh[3*NHB*SEQ*DKV];   // q|k|v hi, head-major [hb][t][e]
__device__ __nv_bfloat16 g_qkvl[3*NHB*SEQ*DKV];   // q|k|v lo
__device__ __nv_bfloat16 g_xhi [NTOK*DMOD];
__device__ __nv_bfloat16 g_xlo [NTOK*DMOD];
__device__ __nv_bfloat16 g_ehi [NTOK*DMOD];
__device__ __nv_bfloat16 g_elo [NTOK*DMOD];
__device__ __nv_bfloat16 g_aohi[NTOK*DMOD];
__device__ __nv_bfloat16 g_aolo[NTOK*DMOD];
__device__ __nv_bfloat16 g_hhi [NTOK*DFF];
__device__ __nv_bfloat16 g_hlo [NTOK*DFF];
__device__ __nv_bfloat16 g_wbhi[(size_t)NL*WL_SIZE];
__device__ __nv_bfloat16 g_wblo[(size_t)NL*WL_SIZE];

struct P6 { const float* p[6]; };

// ---------------- helpers (baseline PTX only: sm_80-class) ----------------
__device__ __forceinline__ uint32_t smem_u32(const void* p) {
    uint32_t a;
    asm("{ .reg .u64 t; cvta.to.shared.u64 t, %1; cvt.u32.u64 %0, t; }" : "=r"(a) : "l"(p));
    return a;
}
__device__ __forceinline__ void cp16(uint32_t saddr, const void* g) {
    asm volatile("cp.async.cg.shared.global [%0], [%1], 16;" :: "r"(saddr), "l"(g));
}
#define CP_COMMIT() asm volatile("cp.async.commit_group;" ::: "memory")
#define CP_WAIT1()  asm volatile("cp.async.wait_group 1;" ::: "memory")
#define CP_WAIT0()  asm volatile("cp.async.wait_group 0;" ::: "memory")

__device__ __forceinline__ void ldsm_x4(uint32_t* r, uint32_t addr) {
    asm volatile("ldmatrix.sync.aligned.m8n8.x4.shared.b16 {%0,%1,%2,%3}, [%4];"
                 : "=r"(r[0]), "=r"(r[1]), "=r"(r[2]), "=r"(r[3]) : "r"(addr));
}
__device__ __forceinline__ void ldsm_x4_t(uint32_t* r, uint32_t addr) {
    asm volatile("ldmatrix.sync.aligned.m8n8.x4.trans.shared.b16 {%0,%1,%2,%3}, [%4];"
                 : "=r"(r[0]), "=r"(r[1]), "=r"(r[2]), "=r"(r[3]) : "r"(addr));
}
__device__ __forceinline__ void mma16816(float* d, const uint32_t* a, const uint32_t* b) {
    asm volatile("mma.sync.aligned.m16n8k16.row.col.f32.bf16.bf16.f32 "
                 "{%0,%1,%2,%3}, {%4,%5,%6,%7}, {%8,%9}, {%0,%1,%2,%3};"
                 : "+f"(d[0]), "+f"(d[1]), "+f"(d[2]), "+f"(d[3])
                 : "r"(a[0]), "r"(a[1]), "r"(a[2]), "r"(a[3]), "r"(b[0]), "r"(b[1]));
}

__device__ __forceinline__ void fsplit(float v, __nv_bfloat16& h, __nv_bfloat16& l) {
    h = __float2bfloat16(v);
    l = __float2bfloat16(v - __bfloat162float(h));
}

// ---------------- embedding (fp32 x + bf16 hi/lo) ----------------
__global__ void embed_k(const int* __restrict__ seq, const int* __restrict__ pos,
                        const float* __restrict__ wemb, const float* __restrict__ pemb,
                        float* __restrict__ x,
                        __nv_bfloat16* __restrict__ xhi, __nv_bfloat16* __restrict__ xlo) {
    int n = blockIdx.x;
    int s = seq[n], p = pos[n];
    const float* we = wemb + (size_t)s * DMOD;
    const float* pe = pemb + (size_t)p * DMOD;
    for (int c = threadIdx.x; c < DMOD; c += blockDim.x) {
        float v = we[c] + pe[c];
        x[(size_t)n * DMOD + c] = v;
        __nv_bfloat16 h, l; fsplit(v, h, l);
        xhi[(size_t)n * DMOD + c] = h;
        xlo[(size_t)n * DMOD + c] = l;
    }
}

// ---------------- fp32 -> bf16 hi/lo split (for enc_output) ----------------
__global__ void conv_split_k(const float* __restrict__ src,
                             __nv_bfloat16* __restrict__ hi, __nv_bfloat16* __restrict__ lo,
                             int n) {
    int i = blockIdx.x * blockDim.x + threadIdx.x;
    if (i < n) {
        __nv_bfloat16 h, l; fsplit(src[i], h, l);
        hi[i] = h; lo[i] = l;
    }
}

// ---------------- batched qkv weight repack (all 6 tensors x 6 layers) ----------------
__global__ void qkv_repack_all(P6 srcs,
                               __nv_bfloat16* __restrict__ dhi_b,
                               __nv_bfloat16* __restrict__ dlo_b) {
    __shared__ float t[64][65];
    const int woff[6] = {WOFF_SQ, WOFF_SK, WOFF_SV, WOFF_EQ, WOFF_EK, WOFF_EV};
    int ti = blockIdx.y, l = blockIdx.z;
    const float* src = srcs.p[ti] + (size_t)l * (NH * DMOD * DKV);
    __nv_bfloat16* dhi = dhi_b + (size_t)l * WL_SIZE + woff[ti];
    __nv_bfloat16* dlo = dlo_b + (size_t)l * WL_SIZE + woff[ti];

    int h = blockIdx.x >> 3, dt = blockIdx.x & 7;
    int d0 = dt * 64;
    int tid = threadIdx.x;
    for (int i = tid; i < 4096; i += 256) {
        int d = i >> 6, e = i & 63;
        t[e][d] = src[h * (DMOD * DKV) + (d0 + d) * DKV + e];
    }
    __syncthreads();
    for (int i = tid; i < 4096; i += 256) {
        int e = i >> 6, d = i & 63;
        __nv_bfloat16 hh, ll; fsplit(t[e][d], hh, ll);
        size_t o = (size_t)(h * 64 + e) * DMOD + d0 + d;
        dhi[o] = hh; dlo[o] = ll;
    }
}

// ---------------- batched projection-weight transpose (slf_pw + enc_pw, all layers) ----------------
__global__ void pw_repack_all(const float* __restrict__ slf_pw, const float* __restrict__ enc_pw,
                              __nv_bfloat16* __restrict__ dhi_b, __nv_bfloat16* __restrict__ dlo_b) {
    __shared__ float t[32][33];
    int z = blockIdx.z, l = z >> 1, te = z & 1;
    const float* src = (te ? enc_pw : slf_pw) + (size_t)l * DMOD * DMOD;
    size_t doff = (size_t)l * WL_SIZE + (te ? WOFF_EPW : WOFF_SPW);
    __nv_bfloat16* dhi = dhi_b + doff;
    __nv_bfloat16* dlo = dlo_b + doff;

    int c0 = blockIdx.x * 32, r0 = blockIdx.y * 32;
    int x = threadIdx.x, y = threadIdx.y;        // 32 x 8
    for (int yy = y; yy < 32; yy += 8)
        t[yy][x] = src[(size_t)(r0 + yy) * DMOD + c0 + x];
    __syncthreads();
    for (int yy = y; yy < 32; yy += 8) {
        __nv_bfloat16 hh, ll; fsplit(t[x][yy], hh, ll);
        size_t o = (size_t)(c0 + yy) * DMOD + r0 + x;
        dhi[o] = hh; dlo[o] = ll;
    }
}

// ---------------- batched FFN weight transpose: [R,C] -> [C,R], all layers via z ----------------
__global__ void ffn_repack_all(const float* __restrict__ w,
                               __nv_bfloat16* __restrict__ dhi_b, __nv_bfloat16* __restrict__ dlo_b,
                               int R, int C, int woff) {
    __shared__ float t[32][33];
    int l = blockIdx.z;
    const float* src = w + (size_t)l * R * C;
    size_t doff = (size_t)l * WL_SIZE + woff;
    __nv_bfloat16* dhi = dhi_b + doff;
    __nv_bfloat16* dlo = dlo_b + doff;

    int c0 = blockIdx.x * 32, r0 = blockIdx.y * 32;
    int x = threadIdx.x, y = threadIdx.y;        // 32 x 8
    for (int yy = y; yy < 32; yy += 8)
        t[yy][x] = src[(size_t)(r0 + yy) * C + c0 + x];
    __syncthreads();
    for (int yy = y; yy < 32; yy += 8) {
        __nv_bfloat16 hh, ll; fsplit(t[x][yy], hh, ll);
        size_t o = (size_t)(c0 + yy) * R + r0 + x;
        dhi[o] = hh; dlo[o] = ll;
    }
}

// ---------------- mma.sync bf16-split GEMM: C[M,N] = A[M,K] @ B[N,K]^T ----------------
// 4 warps, 2x2 warp grid, warp tile 64x64 (smem-traffic-minimal: A x2 + B x2).
// 3 passes: Ahi*Bhi + Ahi*Blo + Alo*Bhi, fp32 register accumulators.
// mode 1: +bias -> fp32 Cf;  mode 2: +bias,relu -> bf16 Chi/Clo;
// mode 3: qkv scatter -> bf16 hi/lo Chi/Clo head-major.
#define GM_PITCH 40                  // bf16 elems per smem row (80B, conflict-free ldmatrix)
#define GM_TILEB (128*GM_PITCH*2)    // 10240 B per 128x32 tile
#define GM_STAGE (4*GM_TILEB)        // Ahi|Alo|Bhi|Blo = 40960 B
#define GM_SMEM  (2*GM_STAGE)        // 81920 B double buffered

__global__ __launch_bounds__(128, 1) void gemm_mma_k(
    const __nv_bfloat16* __restrict__ Ahi, const __nv_bfloat16* __restrict__ Alo,
    const __nv_bfloat16* __restrict__ Bhi, const __nv_bfloat16* __restrict__ Blo,
    const float* __restrict__ bias,
    float* __restrict__ Cf,
    __nv_bfloat16* __restrict__ Chi, __nv_bfloat16* __restrict__ Clo,
    int M, int N, int K, int mode)
{
    extern __shared__ __align__(16) char smem[];
    uint32_t sb = smem_u32(smem);
    const int tid = threadIdx.x, lane = tid & 31, w = tid >> 5;
    const int wm = w >> 1, wn = w & 1;          // warp grid 2 x 2 -> 64 x 64 tiles
    const int n0 = blockIdx.x * 128, m0 = blockIdx.y * 128;

    const __nv_bfloat16* srcs[4] = {
        Ahi + (size_t)m0 * K, Alo + (size_t)m0 * K,
        Bhi + (size_t)n0 * K, Blo + (size_t)n0 * K };

    // loader: 128 threads, each 4 rows x 4 tensors, 16B segs (coalesced 64B groups)
    const int lrow = tid >> 2, lc8 = (tid & 3) * 8;

    auto load_chunk = [&](int kc, int st) {
        const int k0 = kc * 32;
        uint32_t stb = sb + st * GM_STAGE;
#pragma unroll
        for (int t = 0; t < 4; t++) {
            uint32_t tb = stb + t * GM_TILEB;
            const __nv_bfloat16* src = srcs[t] + k0 + lc8;
#pragma unroll
            for (int j = 0; j < 4; j++) {
                int r = lrow + j * 32;
                cp16(tb + (r * GM_PITCH + lc8) * 2, src + (size_t)r * K);
            }
        }
    };

    float acc[4][8][4];
#pragma unroll
    for (int a = 0; a < 4; a++)
#pragma unroll
        for (int b = 0; b < 8; b++)
#pragma unroll
            for (int c = 0; c < 4; c++) acc[a][b][c] = 0.f;

    const int nch = K >> 5;
    load_chunk(0, 0); CP_COMMIT();

    const uint32_t a_off = ((wm * 64 + (lane & 15)) * GM_PITCH + ((lane >> 4) << 3)) * 2;
    const int b_lrow = (lane & 7) + ((lane & 16) ? 8 : 0);
    const int b_lcol = ((lane & 8) ? 8 : 0);

    for (int kc = 0; kc < nch; kc++) {
        if (kc + 1 < nch) { load_chunk(kc + 1, (kc + 1) & 1); CP_COMMIT(); CP_WAIT1(); }
        else { CP_WAIT0(); }
        __syncthreads();

        uint32_t stb = sb + (kc & 1) * GM_STAGE;
#pragma unroll
        for (int ks = 0; ks < 2; ks++) {
            const uint32_t kso = ks * 32;   // 16 elems * 2B
            uint32_t ah[4][4], al[4][4];
#pragma unroll
            for (int mi = 0; mi < 4; mi++) {
                uint32_t off = a_off + mi * 16 * GM_PITCH * 2 + kso;
                ldsm_x4(ah[mi], stb + 0 * GM_TILEB + off);
                ldsm_x4(al[mi], stb + 1 * GM_TILEB + off);
            }
#pragma unroll
            for (int ng = 0; ng < 2; ng++) {
                uint32_t bh[2][4], bl[2][4];
#pragma unroll
                for (int np = 0; np < 2; np++) {
                    uint32_t off = ((wn * 64 + ng * 32 + np * 16 + b_lrow) * GM_PITCH
                                    + b_lcol) * 2 + kso;
                    ldsm_x4(bh[np], stb + 2 * GM_TILEB + off);
                    ldsm_x4(bl[np], stb + 3 * GM_TILEB + off);
                }
#pragma unroll
                for (int mi = 0; mi < 4; mi++)
#pragma unroll
                    for (int nt = 0; nt < 4; nt++) {
                        const uint32_t* bhf = &bh[nt >> 1][(nt & 1) * 2];
                        const uint32_t* blf = &bl[nt >> 1][(nt & 1) * 2];
                        float* ac = acc[mi][ng * 4 + nt];
                        mma16816(ac, ah[mi], bhf);
                        mma16816(ac, ah[mi], blf);
                        mma16816(ac, al[mi], bhf);
                    }
            }
        }
        __syncthreads();
    }

    // epilogue
#pragma unroll
    for (int mi = 0; mi < 4; mi++) {
        int r0 = m0 + wm * 64 + mi * 16 + (lane >> 2);
#pragma unroll
        for (int nj = 0; nj < 8; nj++) {
            int col = n0 + wn * 64 + nj * 8 + (lane & 3) * 2;
            float c0 = acc[mi][nj][0], c1 = acc[mi][nj][1];
            float c2 = acc[mi][nj][2], c3 = acc[mi][nj][3];
            if (mode == 3) {
                int m = col >> 9, hh_ = (col >> 6) & 7, e = col & 63;
#pragma unroll
                for (int rr = 0; rr < 2; rr++) {
                    int row = r0 + rr * 8;
                    int b_ = row >> 9, t = row & 511;
                    size_t off = (size_t)m * 2097152 +
                                 (((size_t)(hh_ * NB + b_) * SEQ + t) * DKV + e);
                    float v0 = rr ? c2 : c0, v1 = rr ? c3 : c1;
                    __nv_bfloat16 h0, l0, h1, l1;
                    fsplit(v0, h0, l0); fsplit(v1, h1, l1);
                    __nv_bfloat162 ph; ph.x = h0; ph.y = h1;
                    __nv_bfloat162 pl; pl.x = l0; pl.y = l1;
                    *(__nv_bfloat162*)(Chi + off) = ph;
                    *(__nv_bfloat162*)(Clo + off) = pl;
                }
            } else if (mode == 1) {
                float2 bv = *(const float2*)(bias + col);
                float2 v0; v0.x = c0 + bv.x; v0.y = c1 + bv.y;
                float2 v1; v1.x = c2 + bv.x; v1.y = c3 + bv.y;
                *(float2*)(Cf + (size_t)r0 * N + col)       = v0;
                *(float2*)(Cf + (size_t)(r0 + 8) * N + col) = v1;
            } else {
                float2 bv = *(const float2*)(bias + col);
                float p0 = fmaxf(c0 + bv.x, 0.f), p1 = fmaxf(c1 + bv.y, 0.f);
                float p2 = fmaxf(c2 + bv.x, 0.f), p3 = fmaxf(c3 + bv.y, 0.f);
                __nv_bfloat16 h0, l0, h1, l1, h2, l2, h3, l3;
                fsplit(p0, h0, l0); fsplit(p1, h1, l1);
                fsplit(p2, h2, l2); fsplit(p3, h3, l3);
                __nv_bfloat162 ph0; ph0.x = h0; ph0.y = h1;
                __nv_bfloat162 ph1; ph1.x = h2; ph1.y = h3;
                __nv_bfloat162 pl0; pl0.x = l0; pl0.y = l1;
                __nv_bfloat162 pl1; pl1.x = l2; pl1.y = l3;
                *(__nv_bfloat162*)(Chi + (size_t)r0 * N + col)       = ph0;
                *(__nv_bfloat162*)(Chi + (size_t)(r0 + 8) * N + col) = ph1;
                *(__nv_bfloat162*)(Clo + (size_t)r0 * N + col)       = pl0;
                *(__nv_bfloat162*)(Clo + (size_t)(r0 + 8) * N + col) = pl1;
            }
        }
    }
}

// ---------------- MMA attention ----------------
// Block = (qt, hb): 64 queries x 512 keys. 8 warps: wm = w&3 (16 rows), wn = w>>2 (half).
#define PT 72                      // bf16 pitch (144 B, 16B-phase conflict-free)
#define SC_PITCH 520
#define SC_OFF   0                 // fp32 [64][520] = 133120 B
#define QH_OFF   133120            // bf16 [64][72] = 9216 B
#define QL_OFF   (QH_OFF + 9216)
#define KV_OFF   (QL_OFF + 9216)   // 2 stages x (hi 9216 + lo 9216)
#define KV_STAGE 18432
#define PTH_OFF  (KV_OFF + 2*KV_STAGE)
#define PTL_OFF  (PTH_OFF + 9216)
#define BIAS_OFF (PTL_OFF + 9216)  // fp32 [512]
#define ATTN2_SMEM (BIAS_OFF + 2048)   // 208896 B

__global__ __launch_bounds__(256, 1) void attn_mma_k(
    const __nv_bfloat16* __restrict__ Qh, const __nv_bfloat16* __restrict__ Ql,
    const __nv_bfloat16* __restrict__ Kh, const __nv_bfloat16* __restrict__ Kl,
    const __nv_bfloat16* __restrict__ Vh, const __nv_bfloat16* __restrict__ Vl,
    const int* __restrict__ seq, float* __restrict__ probs,
    __nv_bfloat16* __restrict__ Ohi, __nv_bfloat16* __restrict__ Olo,
    int causal, int writeProbs)
{
    extern __shared__ __align__(16) char sm2[];
    uint32_t sbase = smem_u32(sm2);
    float* Sc = (float*)(sm2 + SC_OFF);
    float* biasS = (float*)(sm2 + BIAS_OFF);
    const int hb = blockIdx.y, qt = blockIdx.x;
    const int h = hb >> 3, b = hb & 7;
    const int tid = threadIdx.x, lane = tid & 31, w = tid >> 5;
    const int wm = w & 3, wn = w >> 2;
    const float scale = 0.044194173824159216f;   // 1/sqrt(512)

    for (int i = tid; i < 512; i += 256)
        biasS[i] = (seq[b * SEQ + i] == 0) ? -1e30f : 0.f;

    // Q tile -> smem (hi/lo)
    {
        int row = tid >> 2, s0 = (tid & 3) * 16;
        size_t gq = ((size_t)hb * SEQ + qt * 64 + row) * DKV + s0;
        *(uint4*)(sm2 + QH_OFF + (row * PT + s0) * 2)     = *(const uint4*)(Qh + gq);
        *(uint4*)(sm2 + QH_OFF + (row * PT + s0 + 8) * 2) = *(const uint4*)(Qh + gq + 8);
        *(uint4*)(sm2 + QL_OFF + (row * PT + s0) * 2)     = *(const uint4*)(Ql + gq);
        *(uint4*)(sm2 + QL_OFF + (row * PT + s0 + 8) * 2) = *(const uint4*)(Ql + gq + 8);
    }

    auto load_kv = [&](const __nv_bfloat16* Hs, const __nv_bfloat16* Ls, int st, int stage) {
        uint32_t sbst = sbase + KV_OFF + stage * KV_STAGE;
        size_t gbase = ((size_t)hb * SEQ + st * 64) * DKV;
#pragma unroll
        for (int j = 0; j < 2; j++) {
            int seg = tid + j * 256;
            int row = seg >> 3, c = (seg & 7) * 8;
            uint32_t so = sbst + (row * PT + c) * 2;
            cp16(so,        Hs + gbase + row * DKV + c);
            cp16(so + 9216, Ls + gbase + row * DKV + c);
        }
    };

    load_kv(Kh, Kl, 0, 0); CP_COMMIT();
    __syncthreads();

    // resident Q fragments
    uint32_t qhf[4][4], qlf[4][4];
#pragma unroll
    for (int ks = 0; ks < 4; ks++) {
        uint32_t addr = sbase + QH_OFF +
            ((wm * 16 + (lane & 15)) * PT + ks * 16 + ((lane >> 4) << 3)) * 2;
        ldsm_x4(qhf[ks], addr);
        ldsm_x4(qlf[ks], addr + 9216);
    }

    // ---- score phase ----
    for (int st = 0; st < 8; st++) {
        __syncthreads();
        if (st < 7) { load_kv(Kh, Kl, st + 1, (st + 1) & 1); CP_COMMIT(); CP_WAIT1(); }
        else { CP_WAIT0(); }
        __syncthreads();

        uint32_t kb = sbase + KV_OFF + (st & 1) * KV_STAGE;
        float acc[4][4];
#pragma unroll
        for (int i = 0; i < 4; i++)
#pragma unroll
            for (int j = 0; j < 4; j++) acc[i][j] = 0.f;

#pragma unroll
        for (int ks = 0; ks < 4; ks++) {
            uint32_t bh[2][4], bl[2][4];
#pragma unroll
            for (int np = 0; np < 2; np++) {
                uint32_t addr = kb + ((wn * 32 + np * 16 + (lane & 7) + ((lane & 16) ? 8 : 0)) * PT
                                      + ks * 16 + ((lane & 8) ? 8 : 0)) * 2;
                ldsm_x4(bh[np], addr);
                ldsm_x4(bl[np], addr + 9216);
            }
#pragma unroll
            for (int nt = 0; nt < 4; nt++) {
                const uint32_t* bhf = &bh[nt >> 1][(nt & 1) * 2];
                const uint32_t* blf = &bl[nt >> 1][(nt & 1) * 2];
                mma16816(acc[nt], qhf[ks], bhf);
                mma16816(acc[nt], qhf[ks], blf);
                mma16816(acc[nt], qlf[ks], bhf);
            }
        }

        int r0 = wm * 16 + (lane >> 2);
#pragma unroll
        for (int nt = 0; nt < 4; nt++) {
            int col = st * 64 + wn * 32 + nt * 8 + (lane & 3) * 2;
            float b0 = biasS[col], b1 = biasS[col + 1];
#pragma unroll
            for (int rr = 0; rr < 2; rr++) {
                int row = r0 + rr * 8;
                int tg = qt * 64 + row;
                float v0 = acc[nt][rr * 2 + 0] * scale + b0;
                float v1 = acc[nt][rr * 2 + 1] * scale + b1;
                if (causal) {
                    if (col > tg)     v0 = -1e30f;
                    if (col + 1 > tg) v1 = -1e30f;
                }
                float2 vv; vv.x = v0; vv.y = v1;
                *(float2*)(Sc + row * SC_PITCH + col) = vv;
            }
        }
    }
    __syncthreads();

    // ---- softmax (warp per 8 rows) + probs write ----
    {
        for (int r = 0; r < 8; r++) {
            int q = w * 8 + r;
            float* row = Sc + q * SC_PITCH;
            float mx = -3.0e38f;
            for (int c = lane; c < 512; c += 32) mx = fmaxf(mx, row[c]);
#pragma unroll
            for (int o = 16; o; o >>= 1) mx = fmaxf(mx, __shfl_xor_sync(0xffffffffu, mx, o));
            float sum = 0.f;
            for (int c = lane; c < 512; c += 32) {
                float e = __expf(row[c] - mx);
                row[c] = e;
                sum += e;
            }
#pragma unroll
            for (int o = 16; o; o >>= 1) sum += __shfl_xor_sync(0xffffffffu, sum, o);
            float inv = 1.f / sum;
            float* prow = probs + ((size_t)hb * SEQ + qt * 64 + q) * SEQ;
            for (int c = lane; c < 512; c += 32) {
                float p = row[c] * inv;
                row[c] = p;
                if (writeProbs) prow[c] = p;
            }
        }
    }

    // ---- P @ V phase ----
    load_kv(Vh, Vl, 0, 0); CP_COMMIT();
    float oacc[4][4];
#pragma unroll
    for (int i = 0; i < 4; i++)
#pragma unroll
        for (int j = 0; j < 4; j++) oacc[i][j] = 0.f;

    for (int st = 0; st < 8; st++) {
        __syncthreads();
        if (st < 7) { load_kv(Vh, Vl, st + 1, (st + 1) & 1); CP_COMMIT(); CP_WAIT1(); }
        else { CP_WAIT0(); }

        // convert P tile st -> bf16 hi/lo
        {
            int row = tid >> 2, cb = (tid & 3) * 16;
            const float* srow = Sc + row * SC_PITCH + st * 64 + cb;
            __nv_bfloat16* ph = (__nv_bfloat16*)(sm2 + PTH_OFF) + row * PT + cb;
            __nv_bfloat16* pl = (__nv_bfloat16*)(sm2 + PTL_OFF) + row * PT + cb;
#pragma unroll
            for (int j2 = 0; j2 < 16; j2 += 4) {
                float4 p4 = *(const float4*)(srow + j2);
                __nv_bfloat16 h0, l0, h1, l1, h2, l2, h3, l3;
                fsplit(p4.x, h0, l0); fsplit(p4.y, h1, l1);
                fsplit(p4.z, h2, l2); fsplit(p4.w, h3, l3);
                __nv_bfloat162 ha; ha.x = h0; ha.y = h1;
                __nv_bfloat162 hb2; hb2.x = h2; hb2.y = h3;
                __nv_bfloat162 la; la.x = l0; la.y = l1;
                __nv_bfloat162 lb; lb.x = l2; lb.y = l3;
                *(__nv_bfloat162*)(ph + j2)     = ha;
                *(__nv_bfloat162*)(ph + j2 + 2) = hb2;
                *(__nv_bfloat162*)(pl + j2)     = la;
                *(__nv_bfloat162*)(pl + j2 + 2) = lb;
            }
        }
        __syncthreads();

        uint32_t vb = sbase + KV_OFF + (st & 1) * KV_STAGE;
#pragma unroll
        for (int ks = 0; ks < 4; ks++) {
            uint32_t afh[4], afl[4], vbh[2][4], vbl[2][4];
            uint32_t aaddr = sbase + PTH_OFF +
                ((wm * 16 + (lane & 15)) * PT + ks * 16 + ((lane >> 4) << 3)) * 2;
            ldsm_x4(afh, aaddr);
            ldsm_x4(afl, aaddr + 9216);
#pragma unroll
            for (int np = 0; np < 2; np++) {
                uint32_t addr = vb + ((ks * 16 + (lane & 7) + ((lane & 8) ? 8 : 0)) * PT
                                      + wn * 32 + np * 16 + ((lane & 16) ? 8 : 0)) * 2;
                ldsm_x4_t(vbh[np], addr);
                ldsm_x4_t(vbl[np], addr + 9216);
            }
#pragma unroll
            for (int nt = 0; nt < 4; nt++) {
                const uint32_t* bhf = &vbh[nt >> 1][(nt & 1) * 2];
                const uint32_t* blf = &vbl[nt >> 1][(nt & 1) * 2];
                mma16816(oacc[nt], afh, bhf);
                mma16816(oacc[nt], afh, blf);
                mma16816(oacc[nt], afl, bhf);
            }
        }
    }

    // O epilogue -> bf16 hi/lo, layout [b*SEQ+t][h*64+e]
    int r0 = wm * 16 + (lane >> 2);
#pragma unroll
    for (int nt = 0; nt < 4; nt++) {
        int gc = h * DKV + wn * 32 + nt * 8 + (lane & 3) * 2;
#pragma unroll
        for (int rr = 0; rr < 2; rr++) {
            int row = b * SEQ + qt * 64 + r0 + rr * 8;
            float v0 = oacc[nt][rr * 2 + 0], v1 = oacc[nt][rr * 2 + 1];
            __nv_bfloat16 h0, l0, h1, l1;
            fsplit(v0, h0, l0); fsplit(v1, h1, l1);
            __nv_bfloat162 ph; ph.x = h0; ph.y = h1;
            __nv_bfloat162 pl; pl.x = l0; pl.y = l1;
            *(__nv_bfloat162*)(Ohi + (size_t)row * DMOD + gc) = ph;
            *(__nv_bfloat162*)(Olo + (size_t)row * DMOD + gc) = pl;
        }
    }
}

// ---------------- layernorm(y + res) -> fp32 out + bf16 hi/lo ----------------
__global__ __launch_bounds__(128) void ln_k(
    const float* __restrict__ y, const float* __restrict__ res,
    const float* __restrict__ g, const float* __restrict__ b,
    float* __restrict__ out,
    __nv_bfloat16* __restrict__ ohi, __nv_bfloat16* __restrict__ olo)
{
    __shared__ float red[8];
    int n = blockIdx.x, tid = threadIdx.x;
    int c = tid * 4;
    float4 yv = *(const float4*)(y   + (size_t)n * DMOD + c);
    float4 rv = *(const float4*)(res + (size_t)n * DMOD + c);
    float v0 = yv.x + rv.x, v1 = yv.y + rv.y, v2 = yv.z + rv.z, v3 = yv.w + rv.w;

    float s = v0 + v1 + v2 + v3;
    int lane = tid & 31, warp = tid >> 5;
#pragma unroll
    for (int o = 16; o; o >>= 1) s += __shfl_xor_sync(0xffffffffu, s, o);
    if (lane == 0) red[warp] = s;
    __syncthreads();
    float mu = (red[0] + red[1] + red[2] + red[3]) * (1.f / DMOD);

    float d0 = v0 - mu, d1 = v1 - mu, d2 = v2 - mu, d3 = v3 - mu;
    float ss = d0 * d0 + d1 * d1 + d2 * d2 + d3 * d3;
#pragma unroll
    for (int o = 16; o; o >>= 1) ss += __shfl_xor_sync(0xffffffffu, ss, o);
    if (lane == 0) red[4 + warp] = ss;
    __syncthreads();
    float var = (red[4] + red[5] + red[6] + red[7]) * (1.f / DMOD);
    float is = rsqrtf(var + 1e-5f);

    float4 gv = *(const float4*)(g + c);
    float4 bv = *(const float4*)(b + c);
    float4 ov;
    ov.x = d0 * is * gv.x + bv.x;
    ov.y = d1 * is * gv.y + bv.y;
    ov.z = d2 * is * gv.z + bv.z;
    ov.w = d3 * is * gv.w + bv.w;
    *(float4*)(out + (size_t)n * DMOD + c) = ov;

    __nv_bfloat16 h0, l0, h1, l1, h2, l2, h3, l3;
    fsplit(ov.x, h0, l0); fsplit(ov.y, h1, l1);
    fsplit(ov.z, h2, l2); fsplit(ov.w, h3, l3);
    __nv_bfloat162 ph0; ph0.x = h0; ph0.y = h1;
    __nv_bfloat162 ph1; ph1.x = h2; ph1.y = h3;
    __nv_bfloat162 pl0; pl0.x = l0; pl0.y = l1;
    __nv_bfloat162 pl1; pl1.x = l2; pl1.y = l3;
    *(__nv_bfloat162*)(ohi + (size_t)n * DMOD + c)     = ph0;
    *(__nv_bfloat162*)(ohi + (size_t)n * DMOD + c + 2) = ph1;
    *(__nv_bfloat162*)(olo + (size_t)n * DMOD + c)     = pl0;
    *(__nv_bfloat162*)(olo + (size_t)n * DMOD + c + 2) = pl1;
}

// ---------------- host ----------------
extern "C" void kernel_launch(void* const* d_in, const int* in_sizes, int n_in,
                              void* d_out, int out_size)
{
    const int*   tgt_seq = (const int*)d_in[0];
    const int*   tgt_pos = (const int*)d_in[1];
    const int*   src_seq = (const int*)d_in[2];
    const float* enc_out = (const float*)d_in[3];
    const float* tgt_emb = (const float*)d_in[4];
    const float* pos_emb = (const float*)d_in[5];
    const float* slf_wq  = (const float*)d_in[6];
    const float* slf_wk  = (const float*)d_in[7];
    const float* slf_wv  = (const float*)d_in[8];
    const float* slf_pw  = (const float*)d_in[9];
    const float* slf_pb  = (const float*)d_in[10];
    const float* slf_g   = (const float*)d_in[11];
    const float* slf_b   = (const float*)d_in[12];
    const float* enc_wq  = (const float*)d_in[13];
    const float* enc_wk  = (const float*)d_in[14];
    const float* enc_wv  = (const float*)d_in[15];
    const float* enc_pw  = (const float*)d_in[16];
    const float* enc_pb  = (const float*)d_in[17];
    const float* enc_g   = (const float*)d_in[18];
    const float* enc_b   = (const float*)d_in[19];
    const float* ffn_w1  = (const float*)d_in[20];
    const float* ffn_b1  = (const float*)d_in[21];
    const float* ffn_w2  = (const float*)d_in[22];
    const float* ffn_b2  = (const float*)d_in[23];
    const float* ffn_g   = (const float*)d_in[24];
    const float* ffn_b   = (const float*)d_in[25];

    float *xp, *yp;
    __nv_bfloat16 *qkvh, *qkvl, *xhi, *xlo, *ehi, *elo, *aohi, *aolo, *hhi, *hlo, *wbhi, *wblo;
    cudaGetSymbolAddress((void**)&xp,   g_x);
    cudaGetSymbolAddress((void**)&yp,   g_y);
    cudaGetSymbolAddress((void**)&qkvh, g_qkvh);
    cudaGetSymbolAddress((void**)&qkvl, g_qkvl);
    cudaGetSymbolAddress((void**)&xhi,  g_xhi);
    cudaGetSymbolAddress((void**)&xlo,  g_xlo);
    cudaGetSymbolAddress((void**)&ehi,  g_ehi);
    cudaGetSymbolAddress((void**)&elo,  g_elo);
    cudaGetSymbolAddress((void**)&aohi, g_aohi);
    cudaGetSymbolAddress((void**)&aolo, g_aolo);
    cudaGetSymbolAddress((void**)&hhi,  g_hhi);
    cudaGetSymbolAddress((void**)&hlo,  g_hlo);
    cudaGetSymbolAddress((void**)&wbhi, g_wbhi);
    cudaGetSymbolAddress((void**)&wblo, g_wblo);

    cudaFuncSetAttribute(attn_mma_k, cudaFuncAttributeMaxDynamicSharedMemorySize, ATTN2_SMEM);
    cudaFuncSetAttribute(gemm_mma_k, cudaFuncAttributeMaxDynamicSharedMemorySize, GM_SMEM);

    const int full = (out_size >= (int)FULL_OUT) ? 1 : 0;
    float* out_f = (float*)d_out;
    float* probs_slf = out_f + SLF_OFF;
    float* probs_enc = out_f + ENC_OFF;

    __nv_bfloat16* qh = qkvh;
    __nv_bfloat16* kh = qkvh + 2097152;
    __nv_bfloat16* vh = qkvh + 4194304;
    __nv_bfloat16* ql = qkvl;
    __nv_bfloat16* kl = qkvl + 2097152;
    __nv_bfloat16* vl = qkvl + 4194304;

    embed_k<<<NTOK, 128>>>(tgt_seq, tgt_pos, tgt_emb, pos_emb, xp, xhi, xlo);
    conv_split_k<<<(NTOK * DMOD) / 256, 256>>>(enc_out, ehi, elo, NTOK * DMOD);

    // ---- batched weight prep: 4 launches for all 60 repacks ----
    {
        P6 srcs;
        srcs.p[0] = slf_wq; srcs.p[1] = slf_wk; srcs.p[2] = slf_wv;
        srcs.p[3] = enc_wq; srcs.p[4] = enc_wk; srcs.p[5] = enc_wv;
        qkv_repack_all<<<dim3(64, 6, 6), 256>>>(srcs, wbhi, wblo);
        pw_repack_all<<<dim3(16, 16, 12), dim3(32, 8)>>>(slf_pw, enc_pw, wbhi, wblo);
        ffn_repack_all<<<dim3(64, 16, 6), dim3(32, 8)>>>(ffn_w1, wbhi, wblo, DMOD, DFF, WOFF_W1);
        ffn_repack_all<<<dim3(16, 64, 6), dim3(32, 8)>>>(ffn_w2, wbhi, wblo, DFF, DMOD, WOFF_W2);
    }

    dim3 gAttn(8, NHB);

    for (int l = 0; l < NL; l++) {
        size_t LB = (size_t)l * WL_SIZE;

        // ---- self attention: fused QKV (N=1536) ----
        gemm_mma_k<<<dim3(12, 32), 128, GM_SMEM>>>(xhi, xlo,
            wbhi + LB + WOFF_SQ, wblo + LB + WOFF_SQ,
            nullptr, nullptr, qkvh, qkvl, NTOK, 1536, DMOD, 3);
        attn_mma_k<<<gAttn, 256, ATTN2_SMEM>>>(qh, ql, kh, kl, vh, vl, tgt_seq,
            probs_slf + (size_t)l * ATT_PER_L, aohi, aolo, 1, full);
        gemm_mma_k<<<dim3(4, 32), 128, GM_SMEM>>>(aohi, aolo,
            wbhi + LB + WOFF_SPW, wblo + LB + WOFF_SPW,
            slf_pb + (size_t)l * DMOD, yp, nullptr, nullptr, NTOK, DMOD, DMOD, 1);
        ln_k<<<NTOK, 128>>>(yp, xp, slf_g + (size_t)l * DMOD, slf_b + (size_t)l * DMOD,
                            xp, xhi, xlo);

        // ---- cross attention: Q from x (N=512), fused KV from enc (N=1024) ----
        gemm_mma_k<<<dim3(4, 32), 128, GM_SMEM>>>(xhi, xlo,
            wbhi + LB + WOFF_EQ, wblo + LB + WOFF_EQ,
            nullptr, nullptr, qkvh, qkvl, NTOK, DMOD, DMOD, 3);
        gemm_mma_k<<<dim3(8, 32), 128, GM_SMEM>>>(ehi, elo,
            wbhi + LB + WOFF_EK, wblo + LB + WOFF_EK,
            nullptr, nullptr, qkvh + 2097152, qkvl + 2097152, NTOK, 1024, DMOD, 3);
        attn_mma_k<<<gAttn, 256, ATTN2_SMEM>>>(qh, ql, kh, kl, vh, vl, src_seq,
            probs_enc + (size_t)l * ATT_PER_L, aohi, aolo, 0, full);
        gemm_mma_k<<<dim3(4, 32), 128, GM_SMEM>>>(aohi, aolo,
            wbhi + LB + WOFF_EPW, wblo + LB + WOFF_EPW,
            enc_pb + (size_t)l * DMOD, yp, nullptr, nullptr, NTOK, DMOD, DMOD, 1);
        ln_k<<<NTOK, 128>>>(yp, xp, enc_g + (size_t)l * DMOD, enc_b + (size_t)l * DMOD,
                            xp, xhi, xlo);

        // ---- FFN ----
        gemm_mma_k<<<dim3(16, 32), 128, GM_SMEM>>>(xhi, xlo,
            wbhi + LB + WOFF_W1, wblo + LB + WOFF_W1,
            ffn_b1 + (size_t)l * DFF, nullptr, hhi, hlo, NTOK, DFF, DMOD, 2);
        gemm_mma_k<<<dim3(4, 32), 128, GM_SMEM>>>(hhi, hlo,
            wbhi + LB + WOFF_W2, wblo + LB + WOFF_W2,
            ffn_b2 + (size_t)l * DMOD, yp, nullptr, nullptr, NTOK, DMOD, DFF, 1);
        ln_k<<<NTOK, 128>>>(yp, xp, ffn_g + (size_t)l * DMOD, ffn_b + (size_t)l * DMOD,
                            xp, xhi, xlo);
    }

    size_t copy_elems = (size_t)out_size < (size_t)X_ELEMS ? (size_t)out_size : (size_t)X_ELEMS;
    cudaMemcpyAsync(d_out, xp, copy_elems * sizeof(float), cudaMemcpyDeviceToDevice);
}